// round 1
// baseline (speedup 1.0000x reference)
#include <cuda_runtime.h>
#include <math.h>
#include <float.h>

// ---------------- problem constants ----------------
#define G_      32
#define N0      1024
#define EDGES   524288          // 32 * 16384
#define H_      128
#define NT_MAX  32768           // 32 * 1024

static const int NCUR_H[4] = {1024, 820, 656, 525};
static const int KSEL_H[4] = {820, 656, 525, 420};

// ---------------- device scratch (static, no allocation) ----------------
__device__ float g_bufA[NT_MAX * H_];    // h_in for blocks >=2 ; hp output of pooling
__device__ float g_bufB[NT_MAX * H_];    // conv output -> BN'd h
__device__ float g_agg [NT_MAX * H_];
__device__ float g_cnt [NT_MAX];
__device__ float g_invc[NT_MAX];
__device__ int   g_src [EDGES];
__device__ int   g_dst [EDGES];
__device__ float g_score[NT_MAX];
__device__ int   g_map [NT_MAX];
__device__ int   g_perm[NT_MAX];
__device__ float g_colsum[H_];
__device__ float g_colsumsq[H_];
__device__ float g_mu[H_];
__device__ float g_rstd[H_];
__device__ float g_pnorm;
__device__ float g_flat[G_ * 1024];      // [G, 8H]
__device__ float g_hd  [G_ * 512];       // [G, 4H]

// ---------------- kernels ----------------

// zero agg/cnt/colsums, set map = -1
__global__ void prep_kernel(int nt) {
    int i = blockIdx.x * blockDim.x + threadIdx.x;
    int tot = nt * H_;
    if (i < tot) g_agg[i] = 0.f;
    if (i < nt) { g_cnt[i] = 0.f; g_map[i] = -1; }
    if (i < H_) { g_colsum[i] = 0.f; g_colsumsq[i] = 0.f; }
}

// scatter-add of h_in[src] into agg[dst]; one warp per edge (grid-stride)
__global__ void aggregate_kernel(const int* __restrict__ ei, const float* __restrict__ x,
                                 int first) {
    int gwid  = (blockIdx.x * blockDim.x + threadIdx.x) >> 5;
    int lane  = threadIdx.x & 31;
    int nwarp = (gridDim.x * blockDim.x) >> 5;
    const float* hin = first ? x : g_bufA;
    for (int e = gwid; e < EDGES; e += nwarp) {
        int s, d;
        if (first) { s = ei[e]; d = ei[EDGES + e]; }
        else       { s = g_src[e]; d = g_dst[e]; }
        if (s < 0) continue;
        if (lane == 0) atomicAdd(&g_cnt[d], 1.0f);
        const float* hr = hin + (size_t)s * H_;
        float* ar = g_agg + (size_t)d * H_;
        #pragma unroll
        for (int i = 0; i < 4; i++) {
            int c = lane + 32 * i;
            atomicAdd(&ar[c], hr[c]);
        }
    }
}

__global__ void invcnt_kernel(int nt) {
    int i = blockIdx.x * blockDim.x + threadIdx.x;
    if (i < nt) g_invc[i] = 1.0f / fmaxf(g_cnt[i], 1.0f);
}

// h = mean @ Wl + h_in @ Wr + bb ; tile 64 rows x 128 cols, 256 threads, 4x8 per thread
__global__ __launch_bounds__(256)
void gemm_kernel(const float* __restrict__ x, int first,
                 const float* __restrict__ Wl, const float* __restrict__ Wr,
                 const float* __restrict__ bb, int nt) {
    __shared__ float Ash[64][33];
    __shared__ float Wsh[32][128];
    const float* hin = first ? x : g_bufA;
    int row0 = blockIdx.x * 64;
    int tid = threadIdx.x;
    int tx = tid & 15;     // col group: cols tx*8 .. tx*8+7
    int ty = tid >> 4;     // row group: rows ty*4 .. ty*4+3
    float acc[4][8];
    #pragma unroll
    for (int i = 0; i < 4; i++)
        #pragma unroll
        for (int j = 0; j < 8; j++) acc[i][j] = 0.f;

    for (int kb = 0; kb < 256; kb += 32) {
        // stage A chunk (mean for k<128, h_in for k>=128)
        for (int l = tid; l < 64 * 32; l += 256) {
            int r = l >> 5, kk = l & 31;
            int row = row0 + r;
            float v = 0.f;
            if (row < nt) {
                int k = kb + kk;
                if (k < 128) v = g_agg[(size_t)row * H_ + k] * g_invc[row];
                else         v = hin[(size_t)row * H_ + (k - 128)];
            }
            Ash[r][kk] = v;
        }
        // stage W chunk ([Wl;Wr])
        for (int l = tid; l < 32 * 128; l += 256) {
            int kk = l >> 7, c = l & 127;
            int k = kb + kk;
            Wsh[kk][c] = (k < 128) ? Wl[k * H_ + c] : Wr[(k - 128) * H_ + c];
        }
        __syncthreads();
        #pragma unroll
        for (int kk = 0; kk < 32; kk++) {
            float a0 = Ash[ty * 4 + 0][kk];
            float a1 = Ash[ty * 4 + 1][kk];
            float a2 = Ash[ty * 4 + 2][kk];
            float a3 = Ash[ty * 4 + 3][kk];
            float4 w0 = *(const float4*)&Wsh[kk][tx * 8];
            float4 w1 = *(const float4*)&Wsh[kk][tx * 8 + 4];
            float w[8] = {w0.x, w0.y, w0.z, w0.w, w1.x, w1.y, w1.z, w1.w};
            #pragma unroll
            for (int j = 0; j < 8; j++) {
                acc[0][j] += a0 * w[j];
                acc[1][j] += a1 * w[j];
                acc[2][j] += a2 * w[j];
                acc[3][j] += a3 * w[j];
            }
        }
        __syncthreads();
    }
    #pragma unroll
    for (int i = 0; i < 4; i++) {
        int row = row0 + ty * 4 + i;
        if (row < nt) {
            #pragma unroll
            for (int j = 0; j < 8; j++)
                g_bufB[(size_t)row * H_ + tx * 8 + j] = acc[i][j] + bb[tx * 8 + j];
        }
    }
}

// per-column sum and sum-of-squares partials
__global__ void stats_kernel(int nt) {
    int col = threadIdx.x;  // 128
    int chunk = (nt + gridDim.x - 1) / gridDim.x;
    int r0 = blockIdx.x * chunk;
    int r1 = min(nt, r0 + chunk);
    float s = 0.f, q = 0.f;
    for (int r = r0; r < r1; r++) {
        float v = g_bufB[(size_t)r * H_ + col];
        s += v; q += v * v;
    }
    atomicAdd(&g_colsum[col], s);
    atomicAdd(&g_colsumsq[col], q);
}

__global__ void finalize_kernel(const float* __restrict__ p, int nt) {
    int j = threadIdx.x;  // 128
    float inv = 1.0f / (float)nt;
    float mu = g_colsum[j] * inv;
    float var = g_colsumsq[j] * inv - mu * mu;
    g_mu[j] = mu;
    g_rstd[j] = rsqrtf(var + 1e-5f);
    __shared__ float red[128];
    float pv = p[j];
    red[j] = pv * pv;
    __syncthreads();
    for (int s = 64; s > 0; s >>= 1) { if (j < s) red[j] += red[j + s]; __syncthreads(); }
    if (j == 0) g_pnorm = sqrtf(red[0]);
}

// BN apply + ReLU in place, and score = h . p / ||p||
__global__ void bnscore_kernel(const float* __restrict__ gw, const float* __restrict__ be,
                               const float* __restrict__ p, int nt) {
    int row = blockIdx.x;
    if (row >= nt) return;
    int j = threadIdx.x;  // 128
    float v = g_bufB[(size_t)row * H_ + j];
    v = (v - g_mu[j]) * g_rstd[j] * gw[j] + be[j];
    v = fmaxf(v, 0.f);
    g_bufB[(size_t)row * H_ + j] = v;
    __shared__ float red[128];
    red[j] = v * p[j];
    __syncthreads();
    for (int s = 64; s > 0; s >>= 1) { if (j < s) red[j] += red[j + s]; __syncthreads(); }
    if (j == 0) g_score[row] = red[0] / g_pnorm;
}

// per-graph bitonic top-k (descending, tie-break smaller index first)
__global__ __launch_bounds__(512)
void topk_kernel(int ncur, int k) {
    int gph = blockIdx.x;
    __shared__ float s[1024];
    __shared__ int   id[1024];
    for (int i = threadIdx.x; i < 1024; i += 512) {
        if (i < ncur) { s[i] = g_score[gph * ncur + i]; id[i] = i; }
        else          { s[i] = -FLT_MAX;                id[i] = 1024 + i; }
    }
    __syncthreads();
    for (int kk = 2; kk <= 1024; kk <<= 1) {
        for (int j = kk >> 1; j > 0; j >>= 1) {
            for (int i = threadIdx.x; i < 1024; i += 512) {
                int ixj = i ^ j;
                if (ixj > i) {
                    float si = s[i], sj = s[ixj];
                    int ii = id[i], ij = id[ixj];
                    // "i less than ixj" in descending-with-index order
                    bool less = (si < sj) || (si == sj && ii > ij);
                    bool up = ((i & kk) == 0);
                    if (less == up) {
                        s[i] = sj; s[ixj] = si;
                        id[i] = ij; id[ixj] = ii;
                    }
                }
            }
            __syncthreads();
        }
    }
    for (int r = threadIdx.x; r < k; r += 512) {
        int old = gph * ncur + id[r];
        int nw  = gph * k + r;
        g_perm[nw] = old;
        g_map[old] = nw;
    }
}

// hp[new] = h[old] * tanh(score[old])
__global__ void gather_kernel(int nnew) {
    int nw = blockIdx.x;
    if (nw >= nnew) return;
    int j = threadIdx.x;  // 128
    int old = g_perm[nw];
    float t = tanhf(g_score[old]);
    g_bufA[(size_t)nw * H_ + j] = g_bufB[(size_t)old * H_ + j] * t;
}

// re-index edges; drop edges with removed endpoints
__global__ void remap_kernel(const int* __restrict__ ei, int first) {
    int e = blockIdx.x * blockDim.x + threadIdx.x;
    if (e >= EDGES) return;
    int s, d;
    if (first) { s = ei[e]; d = ei[EDGES + e]; }
    else       { s = g_src[e]; d = g_dst[e]; }
    int ns = -1, nd = -1;
    if (s >= 0) {
        ns = g_map[s];
        nd = g_map[d];
        if (ns < 0 || nd < 0) { ns = -1; nd = -1; }
    }
    g_src[e] = ns;
    g_dst[e] = nd;
}

// per-graph [sum || max] readout over k kept nodes
__global__ void readout_kernel(int k, int off) {
    int gph = blockIdx.x;
    int j = threadIdx.x;  // 128
    const float* base = g_bufA + (size_t)gph * k * H_;
    float s = 0.f, m = -FLT_MAX;
    for (int r = 0; r < k; r++) {
        float v = base[(size_t)r * H_ + j];
        s += v;
        m = fmaxf(m, v);
    }
    g_flat[gph * 1024 + off + j]       = s;
    g_flat[gph * 1024 + off + 128 + j] = m;
}

// hd = relu(flat @ Wd1 + bd1) : [32,1024]x[1024,512]
__global__ void dense1_kernel(const float* __restrict__ Wd1, const float* __restrict__ bd1) {
    int gph = blockIdx.x;
    int j = blockIdx.y * 256 + threadIdx.x;  // 0..511
    __shared__ float a[1024];
    for (int i = threadIdx.x; i < 1024; i += 256) a[i] = g_flat[gph * 1024 + i];
    __syncthreads();
    float acc = bd1[j];
    #pragma unroll 8
    for (int kk = 0; kk < 1024; kk++) acc += a[kk] * Wd1[kk * 512 + j];
    g_hd[gph * 512 + j] = fmaxf(acc, 0.f);
}

// out = hd @ Wd2 + bd2 : [32,512]x[512,10]
__global__ void dense2_kernel(const float* __restrict__ Wd2, const float* __restrict__ bd2,
                              float* __restrict__ out) {
    int gph = blockIdx.x;
    int c = threadIdx.x >> 5;   // 0..9 (blockDim 320)
    int lane = threadIdx.x & 31;
    if (c >= 10) return;
    float acc = 0.f;
    for (int kk = lane; kk < 512; kk += 32) acc += g_hd[gph * 512 + kk] * Wd2[kk * 10 + c];
    #pragma unroll
    for (int o = 16; o > 0; o >>= 1) acc += __shfl_down_sync(0xffffffff, acc, o);
    if (lane == 0) out[gph * 10 + c] = acc + bd2[c];
}

// ---------------- launcher ----------------
extern "C" void kernel_launch(void* const* d_in, const int* in_sizes, int n_in,
                              void* d_out, int out_size) {
    const float* x  = (const float*)d_in[0];
    const int*   ei = (const int*)d_in[1];
    // d_in[2] = batch (unused: graphs are contiguous, equal-size)
    const float *Wl[4], *Wr[4], *bb[4], *gw[4], *be[4], *pp[4];
    int idx = 3;
    for (int b = 0; b < 4; b++) {
        Wl[b] = (const float*)d_in[idx++];
        Wr[b] = (const float*)d_in[idx++];
        bb[b] = (const float*)d_in[idx++];
        gw[b] = (const float*)d_in[idx++];
        be[b] = (const float*)d_in[idx++];
        pp[b] = (const float*)d_in[idx++];
    }
    const float* Wd1 = (const float*)d_in[27];
    const float* bd1 = (const float*)d_in[28];
    const float* Wd2 = (const float*)d_in[29];
    const float* bd2 = (const float*)d_in[30];
    float* out = (float*)d_out;

    for (int b = 0; b < 4; b++) {
        int ncur = NCUR_H[b];
        int k    = KSEL_H[b];
        int nt   = G_ * ncur;
        int first = (b == 0) ? 1 : 0;

        prep_kernel<<<(nt * H_ + 255) / 256, 256>>>(nt);
        aggregate_kernel<<<2048, 256>>>(ei, x, first);
        invcnt_kernel<<<(nt + 255) / 256, 256>>>(nt);
        gemm_kernel<<<(nt + 63) / 64, 256>>>(x, first, Wl[b], Wr[b], bb[b], nt);
        stats_kernel<<<128, 128>>>(nt);
        finalize_kernel<<<1, 128>>>(pp[b], nt);
        bnscore_kernel<<<nt, 128>>>(gw[b], be[b], pp[b], nt);
        topk_kernel<<<G_, 512>>>(ncur, k);
        gather_kernel<<<G_ * k, 128>>>(G_ * k);
        if (b < 3) remap_kernel<<<(EDGES + 255) / 256, 256>>>(ei, first);
        readout_kernel<<<G_, 128>>>(k, b * 256);
    }
    dense1_kernel<<<dim3(G_, 2), 256>>>(Wd1, bd1);
    dense2_kernel<<<G_, 320>>>(Wd2, bd2, out);
}

// round 2
// speedup vs baseline: 1.3583x; 1.3583x over previous
#include <cuda_runtime.h>
#include <math.h>
#include <float.h>

// ---------------- problem constants ----------------
#define G_      32
#define N0      1024
#define EDGES   524288          // 32 * 16384
#define H_      128
#define NT_MAX  32768           // 32 * 1024

static const int NCUR_H[4] = {1024, 820, 656, 525};
static const int KSEL_H[4] = {820, 656, 525, 420};

// ---------------- device scratch (static, no allocation) ----------------
__device__ float g_bufA[NT_MAX * H_];    // h_in for blocks >=2 ; hp output of pooling
__device__ float g_bufB[NT_MAX * H_];    // conv output -> BN'd h
__device__ float g_mean[NT_MAX * H_];    // mean aggregate
__device__ int   g_cnti[NT_MAX];         // in-degree
__device__ int   g_off [NT_MAX];         // local exclusive offsets (within 1024-chunk)
__device__ int   g_fill[NT_MAX];         // fill cursors
__device__ int   g_bsum[32];             // per-chunk totals
__device__ int   g_bpre[32];             // chunk prefix
__device__ int   g_csr [EDGES];          // src ids grouped by dst
__device__ int   g_src [EDGES];
__device__ int   g_dst [EDGES];
__device__ float g_score[NT_MAX];
__device__ int   g_map [NT_MAX];
__device__ int   g_perm[NT_MAX];
__device__ float g_colsum[H_];
__device__ float g_colsumsq[H_];
__device__ float g_mu[H_];
__device__ float g_rstd[H_];
__device__ float g_pnorm;
__device__ float g_flat[G_ * 1024];      // [G, 8H]
__device__ float g_hd  [G_ * 512];       // [G, 4H]

// ---------------- kernels ----------------

// zero counters, set map = -1
__global__ void prep_kernel(int nt) {
    int i = blockIdx.x * blockDim.x + threadIdx.x;
    if (i < nt) { g_cnti[i] = 0; g_fill[i] = 0; g_map[i] = -1; }
    if (i < H_) { g_colsum[i] = 0.f; g_colsumsq[i] = 0.f; }
}

// in-degree histogram
__global__ void count_kernel(const int* __restrict__ ei, int first) {
    int e = blockIdx.x * blockDim.x + threadIdx.x;
    if (e >= EDGES) return;
    int s, d;
    if (first) { s = ei[e]; d = ei[EDGES + e]; }
    else       { s = g_src[e]; d = g_dst[e]; }
    if (s >= 0) atomicAdd(&g_cnti[d], 1);
}

// per-1024-chunk inclusive scan -> exclusive offsets + chunk totals
__global__ __launch_bounds__(1024)
void scan_kernel(int nt) {
    __shared__ int sm[1024];
    int i = blockIdx.x * 1024 + threadIdx.x;
    int v = (i < nt) ? g_cnti[i] : 0;
    sm[threadIdx.x] = v;
    __syncthreads();
    for (int off = 1; off < 1024; off <<= 1) {
        int t = (threadIdx.x >= off) ? sm[threadIdx.x - off] : 0;
        __syncthreads();
        sm[threadIdx.x] += t;
        __syncthreads();
    }
    if (i < nt) g_off[i] = sm[threadIdx.x] - v;
    if (threadIdx.x == 1023) g_bsum[blockIdx.x] = sm[1023];
}

__global__ void scan2_kernel(int nblk) {
    if (threadIdx.x == 0) {
        int acc = 0;
        for (int b = 0; b < nblk; b++) { g_bpre[b] = acc; acc += g_bsum[b]; }
    }
}

// scatter edge src ids into CSR slots of their dst
__global__ void fill_kernel(const int* __restrict__ ei, int first) {
    int e = blockIdx.x * blockDim.x + threadIdx.x;
    if (e >= EDGES) return;
    int s, d;
    if (first) { s = ei[e]; d = ei[EDGES + e]; }
    else       { s = g_src[e]; d = g_dst[e]; }
    if (s < 0) return;
    int pos = atomicAdd(&g_fill[d], 1);
    g_csr[g_off[d] + g_bpre[d >> 10] + pos] = s;
}

// one warp per dst node: gather-sum neighbor rows, write mean
__global__ __launch_bounds__(256)
void gatheragg_kernel(const float* __restrict__ x, int first, int nt) {
    int warp = (blockIdx.x * blockDim.x + threadIdx.x) >> 5;
    int lane = threadIdx.x & 31;
    if (warp >= nt) return;
    const float* hin = first ? x : g_bufA;
    int deg  = g_cnti[warp];
    int base = g_off[warp] + g_bpre[warp >> 10];
    float s0 = 0.f, s1 = 0.f, s2 = 0.f, s3 = 0.f;
    for (int j0 = 0; j0 < deg; j0 += 32) {
        int myi = j0 + lane;
        int srcv = (myi < deg) ? g_csr[base + myi] : 0;
        int lim = min(32, deg - j0);
        for (int j = 0; j < lim; j++) {
            int sr = __shfl_sync(0xffffffff, srcv, j);
            const float* hr = hin + (size_t)sr * H_;
            s0 += hr[lane];
            s1 += hr[lane + 32];
            s2 += hr[lane + 64];
            s3 += hr[lane + 96];
        }
    }
    float inv = 1.0f / fmaxf((float)deg, 1.0f);
    float* mr = g_mean + (size_t)warp * H_;
    mr[lane]      = s0 * inv;
    mr[lane + 32] = s1 * inv;
    mr[lane + 64] = s2 * inv;
    mr[lane + 96] = s3 * inv;
}

// h = [mean||h_in] @ [Wl;Wr] + bb
// 128x128 tile, BK=16, 256 threads, 8x8 per thread, reg-prefetch pipeline
#define BK 16
__global__ __launch_bounds__(256, 2)
void gemm_kernel(const float* __restrict__ x, int first,
                 const float* __restrict__ Wl, const float* __restrict__ Wr,
                 const float* __restrict__ bb, int nt) {
    __shared__ float Ash[BK][128];   // K-major: Ash[k][m]
    __shared__ float Wsh[BK][128];   // Wsh[k][n]
    const float* hin = first ? x : g_bufA;
    int row0 = blockIdx.x * 128;
    int tid = threadIdx.x;
    int tx = tid & 15, ty = tid >> 4;
    int rm = ty * 4, cn = tx * 4;
    float acc[8][8];
    #pragma unroll
    for (int i = 0; i < 8; i++)
        #pragma unroll
        for (int j = 0; j < 8; j++) acc[i][j] = 0.f;

    float4 pa[2], pw[2];

    // prefetch kb = 0
    #pragma unroll
    for (int i = 0; i < 2; i++) {
        int idx = tid * 2 + i;
        int r = idx >> 2, kc = (idx & 3) * 4;     // A: row r, k-col kc (k = 0+kc < 128 -> mean)
        int row = row0 + r;
        float4 v = make_float4(0.f, 0.f, 0.f, 0.f);
        if (row < nt) v = *(const float4*)(g_mean + (size_t)row * H_ + kc);
        pa[i] = v;
        int kk = idx >> 5, c = (idx & 31) * 4;    // W: k-row kk, col c
        pw[i] = *(const float4*)(Wl + (size_t)kk * H_ + c);
    }

    for (int kbi = 0; kbi < 16; kbi++) {
        // store prefetched regs to smem (A transposed)
        #pragma unroll
        for (int i = 0; i < 2; i++) {
            int idx = tid * 2 + i;
            int r = idx >> 2, kc = (idx & 3) * 4;
            Ash[kc + 0][r] = pa[i].x;
            Ash[kc + 1][r] = pa[i].y;
            Ash[kc + 2][r] = pa[i].z;
            Ash[kc + 3][r] = pa[i].w;
            int kk = idx >> 5, c = (idx & 31) * 4;
            *(float4*)&Wsh[kk][c] = pw[i];
        }
        __syncthreads();

        // prefetch next k-block
        if (kbi < 15) {
            int kb = (kbi + 1) * BK;
            #pragma unroll
            for (int i = 0; i < 2; i++) {
                int idx = tid * 2 + i;
                int r = idx >> 2, kc = (idx & 3) * 4;
                int row = row0 + r;
                int k = kb + kc;
                float4 v = make_float4(0.f, 0.f, 0.f, 0.f);
                if (row < nt) {
                    const float* src = (k < 128)
                        ? (g_mean + (size_t)row * H_ + k)
                        : (hin    + (size_t)row * H_ + (k - 128));
                    v = *(const float4*)src;
                }
                pa[i] = v;
                int kk = idx >> 5, c = (idx & 31) * 4;
                int kw = kb + kk;
                const float* ws = (kw < 128)
                    ? (Wl + (size_t)kw * H_ + c)
                    : (Wr + (size_t)(kw - 128) * H_ + c);
                pw[i] = *(const float4*)ws;
            }
        }

        // compute
        #pragma unroll
        for (int kk = 0; kk < BK; kk++) {
            float4 a0 = *(const float4*)&Ash[kk][rm];
            float4 a1 = *(const float4*)&Ash[kk][rm + 64];
            float4 b0 = *(const float4*)&Wsh[kk][cn];
            float4 b1 = *(const float4*)&Wsh[kk][cn + 64];
            float a[8] = {a0.x, a0.y, a0.z, a0.w, a1.x, a1.y, a1.z, a1.w};
            float b[8] = {b0.x, b0.y, b0.z, b0.w, b1.x, b1.y, b1.z, b1.w};
            #pragma unroll
            for (int i = 0; i < 8; i++)
                #pragma unroll
                for (int j = 0; j < 8; j++)
                    acc[i][j] += a[i] * b[j];
        }
        __syncthreads();
    }

    // epilogue
    float4 bia0 = *(const float4*)&bb[cn];
    float4 bia1 = *(const float4*)&bb[cn + 64];
    #pragma unroll
    for (int i = 0; i < 8; i++) {
        int row = row0 + ((i < 4) ? (rm + i) : (64 + rm + i - 4));
        if (row < nt) {
            float4 v0 = make_float4(acc[i][0] + bia0.x, acc[i][1] + bia0.y,
                                    acc[i][2] + bia0.z, acc[i][3] + bia0.w);
            float4 v1 = make_float4(acc[i][4] + bia1.x, acc[i][5] + bia1.y,
                                    acc[i][6] + bia1.z, acc[i][7] + bia1.w);
            *(float4*)(g_bufB + (size_t)row * H_ + cn)      = v0;
            *(float4*)(g_bufB + (size_t)row * H_ + cn + 64) = v1;
        }
    }
}

// per-column sum and sum-of-squares partials
__global__ void stats_kernel(int nt) {
    int col = threadIdx.x;  // 128
    int chunk = (nt + gridDim.x - 1) / gridDim.x;
    int r0 = blockIdx.x * chunk;
    int r1 = min(nt, r0 + chunk);
    float s = 0.f, q = 0.f;
    for (int r = r0; r < r1; r++) {
        float v = g_bufB[(size_t)r * H_ + col];
        s += v; q += v * v;
    }
    atomicAdd(&g_colsum[col], s);
    atomicAdd(&g_colsumsq[col], q);
}

__global__ void finalize_kernel(const float* __restrict__ p, int nt) {
    int j = threadIdx.x;  // 128
    float inv = 1.0f / (float)nt;
    float mu = g_colsum[j] * inv;
    float var = g_colsumsq[j] * inv - mu * mu;
    g_mu[j] = mu;
    g_rstd[j] = rsqrtf(var + 1e-5f);
    __shared__ float red[128];
    float pv = p[j];
    red[j] = pv * pv;
    __syncthreads();
    for (int s = 64; s > 0; s >>= 1) { if (j < s) red[j] += red[j + s]; __syncthreads(); }
    if (j == 0) g_pnorm = sqrtf(red[0]);
}

// BN apply + ReLU in place, and score = h . p / ||p||
__global__ void bnscore_kernel(const float* __restrict__ gw, const float* __restrict__ be,
                               const float* __restrict__ p, int nt) {
    int row = blockIdx.x;
    if (row >= nt) return;
    int j = threadIdx.x;  // 128
    float v = g_bufB[(size_t)row * H_ + j];
    v = (v - g_mu[j]) * g_rstd[j] * gw[j] + be[j];
    v = fmaxf(v, 0.f);
    g_bufB[(size_t)row * H_ + j] = v;
    __shared__ float red[128];
    red[j] = v * p[j];
    __syncthreads();
    for (int s = 64; s > 0; s >>= 1) { if (j < s) red[j] += red[j + s]; __syncthreads(); }
    if (j == 0) g_score[row] = red[0] / g_pnorm;
}

// per-graph bitonic top-k (descending, tie-break smaller index first)
__global__ __launch_bounds__(512)
void topk_kernel(int ncur, int k) {
    int gph = blockIdx.x;
    __shared__ float s[1024];
    __shared__ int   id[1024];
    for (int i = threadIdx.x; i < 1024; i += 512) {
        if (i < ncur) { s[i] = g_score[gph * ncur + i]; id[i] = i; }
        else          { s[i] = -FLT_MAX;                id[i] = 1024 + i; }
    }
    __syncthreads();
    for (int kk = 2; kk <= 1024; kk <<= 1) {
        for (int j = kk >> 1; j > 0; j >>= 1) {
            for (int i = threadIdx.x; i < 1024; i += 512) {
                int ixj = i ^ j;
                if (ixj > i) {
                    float si = s[i], sj = s[ixj];
                    int ii = id[i], ij = id[ixj];
                    bool less = (si < sj) || (si == sj && ii > ij);
                    bool up = ((i & kk) == 0);
                    if (less == up) {
                        s[i] = sj; s[ixj] = si;
                        id[i] = ij; id[ixj] = ii;
                    }
                }
            }
            __syncthreads();
        }
    }
    for (int r = threadIdx.x; r < k; r += 512) {
        int old = gph * ncur + id[r];
        int nw  = gph * k + r;
        g_perm[nw] = old;
        g_map[old] = nw;
    }
}

// hp[new] = h[old] * tanh(score[old])
__global__ void gather_kernel(int nnew) {
    int nw = blockIdx.x;
    if (nw >= nnew) return;
    int j = threadIdx.x;  // 128
    int old = g_perm[nw];
    float t = tanhf(g_score[old]);
    g_bufA[(size_t)nw * H_ + j] = g_bufB[(size_t)old * H_ + j] * t;
}

// re-index edges; drop edges with removed endpoints
__global__ void remap_kernel(const int* __restrict__ ei, int first) {
    int e = blockIdx.x * blockDim.x + threadIdx.x;
    if (e >= EDGES) return;
    int s, d;
    if (first) { s = ei[e]; d = ei[EDGES + e]; }
    else       { s = g_src[e]; d = g_dst[e]; }
    int ns = -1, nd = -1;
    if (s >= 0) {
        ns = g_map[s];
        nd = g_map[d];
        if (ns < 0 || nd < 0) { ns = -1; nd = -1; }
    }
    g_src[e] = ns;
    g_dst[e] = nd;
}

// per-graph [sum || max] readout over k kept nodes
__global__ void readout_kernel(int k, int off) {
    int gph = blockIdx.x;
    int j = threadIdx.x;  // 128
    const float* base = g_bufA + (size_t)gph * k * H_;
    float s = 0.f, m = -FLT_MAX;
    for (int r = 0; r < k; r++) {
        float v = base[(size_t)r * H_ + j];
        s += v;
        m = fmaxf(m, v);
    }
    g_flat[gph * 1024 + off + j]       = s;
    g_flat[gph * 1024 + off + 128 + j] = m;
}

// hd = relu(flat @ Wd1 + bd1) : [32,1024]x[1024,512]
__global__ void dense1_kernel(const float* __restrict__ Wd1, const float* __restrict__ bd1) {
    int gph = blockIdx.x;
    int j = blockIdx.y * 256 + threadIdx.x;  // 0..511
    __shared__ float a[1024];
    for (int i = threadIdx.x; i < 1024; i += 256) a[i] = g_flat[gph * 1024 + i];
    __syncthreads();
    float acc = bd1[j];
    #pragma unroll 8
    for (int kk = 0; kk < 1024; kk++) acc += a[kk] * Wd1[kk * 512 + j];
    g_hd[gph * 512 + j] = fmaxf(acc, 0.f);
}

// out = hd @ Wd2 + bd2 : [32,512]x[512,10]
__global__ void dense2_kernel(const float* __restrict__ Wd2, const float* __restrict__ bd2,
                              float* __restrict__ out) {
    int gph = blockIdx.x;
    int c = threadIdx.x >> 5;   // 0..9 (blockDim 320)
    int lane = threadIdx.x & 31;
    if (c >= 10) return;
    float acc = 0.f;
    for (int kk = lane; kk < 512; kk += 32) acc += g_hd[gph * 512 + kk] * Wd2[kk * 10 + c];
    #pragma unroll
    for (int o = 16; o > 0; o >>= 1) acc += __shfl_down_sync(0xffffffff, acc, o);
    if (lane == 0) out[gph * 10 + c] = acc + bd2[c];
}

// ---------------- launcher ----------------
extern "C" void kernel_launch(void* const* d_in, const int* in_sizes, int n_in,
                              void* d_out, int out_size) {
    const float* x  = (const float*)d_in[0];
    const int*   ei = (const int*)d_in[1];
    const float *Wl[4], *Wr[4], *bb[4], *gw[4], *be[4], *pp[4];
    int idx = 3;
    for (int b = 0; b < 4; b++) {
        Wl[b] = (const float*)d_in[idx++];
        Wr[b] = (const float*)d_in[idx++];
        bb[b] = (const float*)d_in[idx++];
        gw[b] = (const float*)d_in[idx++];
        be[b] = (const float*)d_in[idx++];
        pp[b] = (const float*)d_in[idx++];
    }
    const float* Wd1 = (const float*)d_in[27];
    const float* bd1 = (const float*)d_in[28];
    const float* Wd2 = (const float*)d_in[29];
    const float* bd2 = (const float*)d_in[30];
    float* out = (float*)d_out;

    for (int b = 0; b < 4; b++) {
        int ncur = NCUR_H[b];
        int k    = KSEL_H[b];
        int nt   = G_ * ncur;
        int first = (b == 0) ? 1 : 0;
        int nchunks = (nt + 1023) / 1024;

        prep_kernel<<<(nt + 255) / 256, 256>>>(nt);
        count_kernel<<<(EDGES + 255) / 256, 256>>>(ei, first);
        scan_kernel<<<nchunks, 1024>>>(nt);
        scan2_kernel<<<1, 32>>>(nchunks);
        fill_kernel<<<(EDGES + 255) / 256, 256>>>(ei, first);
        gatheragg_kernel<<<(nt + 7) / 8, 256>>>(x, first, nt);
        gemm_kernel<<<(nt + 127) / 128, 256>>>(x, first, Wl[b], Wr[b], bb[b], nt);
        stats_kernel<<<128, 128>>>(nt);
        finalize_kernel<<<1, 128>>>(pp[b], nt);
        bnscore_kernel<<<nt, 128>>>(gw[b], be[b], pp[b], nt);
        topk_kernel<<<G_, 512>>>(ncur, k);
        gather_kernel<<<G_ * k, 128>>>(G_ * k);
        if (b < 3) remap_kernel<<<(EDGES + 255) / 256, 256>>>(ei, first);
        readout_kernel<<<G_, 128>>>(k, b * 256);
    }
    dense1_kernel<<<dim3(G_, 2), 256>>>(Wd1, bd1);
    dense2_kernel<<<G_, 320>>>(Wd2, bd2, out);
}

// round 3
// speedup vs baseline: 1.6938x; 1.2470x over previous
#include <cuda_runtime.h>
#include <math.h>
#include <float.h>

// ---------------- problem constants ----------------
#define G_      32
#define N0      1024
#define EDGES   524288          // 32 * 16384
#define H_      128
#define NT_MAX  32768           // 32 * 1024

static const int NCUR_H[4] = {1024, 820, 656, 525};
static const int KSEL_H[4] = {820, 656, 525, 420};

// ---------------- device scratch (static, no allocation) ----------------
__device__ __align__(16) float g_bufA[NT_MAX * H_];    // h_in for blocks >=2 ; hp output of pooling
__device__ __align__(16) float g_bufB[NT_MAX * H_];    // conv output -> BN'd h
__device__ __align__(16) float g_mean[NT_MAX * H_];    // mean aggregate
__device__ int   g_cnti[NT_MAX];         // in-degree
__device__ int   g_off [NT_MAX];         // local exclusive offsets (within 1024-chunk)
__device__ int   g_fill[NT_MAX];         // fill cursors
__device__ int   g_bsum[32];             // per-chunk totals
__device__ int   g_bpre[32];             // chunk prefix
__device__ int   g_tick;                 // scan ticket (self-resetting)
__device__ int   g_csr [EDGES];          // src ids grouped by dst
__device__ int   g_src [EDGES];
__device__ int   g_dst [EDGES];
__device__ float g_score[NT_MAX];
__device__ int   g_map [NT_MAX];         // (epoch<<16) | new_id
__device__ int   g_perm[NT_MAX];
__device__ __align__(16) float g_colsum[H_];
__device__ __align__(16) float g_colsumsq[H_];
__device__ float g_flat[G_ * 1024];      // [G, 8H]
__device__ float g_hd  [G_ * 512];       // [G, 4H]

// ---------------- kernels ----------------

// block-0 only: zero counters & colsums
__global__ void prep_kernel(int nt) {
    int i = blockIdx.x * blockDim.x + threadIdx.x;
    if (i < nt) { g_cnti[i] = 0; g_fill[i] = 0; }
    if (i < H_) { g_colsum[i] = 0.f; g_colsumsq[i] = 0.f; }
}

// block-0 only: in-degree histogram from input edges (all valid)
__global__ void count_kernel(const int* __restrict__ ei) {
    int e = blockIdx.x * blockDim.x + threadIdx.x;
    if (e >= EDGES) return;
    atomicAdd(&g_cnti[ei[EDGES + e]], 1);
}

// per-1024-chunk scan + decoupled level-2 prefix (last block computes g_bpre)
__global__ __launch_bounds__(1024)
void scan_kernel(int nt, int nblk) {
    __shared__ int sm[1024];
    __shared__ int amlast;
    int tid = threadIdx.x;
    int i = blockIdx.x * 1024 + tid;
    int v = (i < nt) ? g_cnti[i] : 0;
    sm[tid] = v;
    __syncthreads();
    for (int off = 1; off < 1024; off <<= 1) {
        int t = (tid >= off) ? sm[tid - off] : 0;
        __syncthreads();
        sm[tid] += t;
        __syncthreads();
    }
    if (i < nt) g_off[i] = sm[tid] - v;
    if (tid == 1023) {
        g_bsum[blockIdx.x] = sm[1023];
        __threadfence();
        int t = atomicAdd(&g_tick, 1);
        amlast = (t == nblk - 1) ? 1 : 0;
    }
    __syncthreads();
    if (tid == 0 && amlast) {
        volatile int* vb = g_bsum;
        int acc = 0;
        for (int b = 0; b < nblk; b++) { g_bpre[b] = acc; acc += vb[b]; }
        g_tick = 0;
    }
}

// scatter edge src ids into CSR slots of their dst
__global__ void fill_kernel(const int* __restrict__ ei, int first) {
    int e = blockIdx.x * blockDim.x + threadIdx.x;
    if (e >= EDGES) return;
    int s, d;
    if (first) { s = ei[e]; d = ei[EDGES + e]; }
    else       { s = g_src[e]; d = g_dst[e]; }
    if (s < 0) return;
    int pos = atomicAdd(&g_fill[d], 1);
    g_csr[g_off[d] + g_bpre[d >> 10] + pos] = s;
}

// one warp per dst node: gather-sum neighbor rows (float4/lane), write mean
__global__ __launch_bounds__(256)
void gatheragg_kernel(const float* __restrict__ x, int first, int nt) {
    int node = (blockIdx.x * blockDim.x + threadIdx.x) >> 5;
    int lane = threadIdx.x & 31;
    if (node >= nt) return;
    const float* hin = first ? x : g_bufA;
    int deg  = g_cnti[node];
    int base = g_off[node] + g_bpre[node >> 10];
    float4 acc = make_float4(0.f, 0.f, 0.f, 0.f);
    int j = 0;
    for (; j + 4 <= deg; j += 4) {
        int s0 = g_csr[base + j];
        int s1 = g_csr[base + j + 1];
        int s2 = g_csr[base + j + 2];
        int s3 = g_csr[base + j + 3];
        float4 a = *((const float4*)(hin + (size_t)s0 * H_) + lane);
        float4 b = *((const float4*)(hin + (size_t)s1 * H_) + lane);
        float4 c = *((const float4*)(hin + (size_t)s2 * H_) + lane);
        float4 d = *((const float4*)(hin + (size_t)s3 * H_) + lane);
        acc.x += a.x + b.x + c.x + d.x;
        acc.y += a.y + b.y + c.y + d.y;
        acc.z += a.z + b.z + c.z + d.z;
        acc.w += a.w + b.w + c.w + d.w;
    }
    for (; j < deg; j++) {
        int s0 = g_csr[base + j];
        float4 a = *((const float4*)(hin + (size_t)s0 * H_) + lane);
        acc.x += a.x; acc.y += a.y; acc.z += a.z; acc.w += a.w;
    }
    float inv = 1.0f / fmaxf((float)deg, 1.0f);
    acc.x *= inv; acc.y *= inv; acc.z *= inv; acc.w *= inv;
    *((float4*)(g_mean + (size_t)node * H_) + lane) = acc;
}

// h = [mean||h_in] @ [Wl;Wr] + bb, fused BN column sums (atomics)
#define BK 16
__global__ __launch_bounds__(256, 2)
void gemm_kernel(const float* __restrict__ x, int first,
                 const float* __restrict__ Wl, const float* __restrict__ Wr,
                 const float* __restrict__ bb, int nt) {
    __shared__ float Ash[BK][128];   // K-major: Ash[k][m] ; reused as col-sum partials
    __shared__ float Wsh[BK][128];   // Wsh[k][n]          ; reused as col-sq partials
    const float* hin = first ? x : g_bufA;
    int row0 = blockIdx.x * 128;
    int tid = threadIdx.x;
    int tx = tid & 15, ty = tid >> 4;
    int rm = ty * 4, cn = tx * 4;
    float acc[8][8];
    #pragma unroll
    for (int i = 0; i < 8; i++)
        #pragma unroll
        for (int j = 0; j < 8; j++) acc[i][j] = 0.f;

    float4 pa[2], pw[2];

    #pragma unroll
    for (int i = 0; i < 2; i++) {
        int idx = tid * 2 + i;
        int r = idx >> 2, kc = (idx & 3) * 4;
        int row = row0 + r;
        float4 v = make_float4(0.f, 0.f, 0.f, 0.f);
        if (row < nt) v = *(const float4*)(g_mean + (size_t)row * H_ + kc);
        pa[i] = v;
        int kk = idx >> 5, c = (idx & 31) * 4;
        pw[i] = *(const float4*)(Wl + (size_t)kk * H_ + c);
    }

    for (int kbi = 0; kbi < 16; kbi++) {
        #pragma unroll
        for (int i = 0; i < 2; i++) {
            int idx = tid * 2 + i;
            int r = idx >> 2, kc = (idx & 3) * 4;
            Ash[kc + 0][r] = pa[i].x;
            Ash[kc + 1][r] = pa[i].y;
            Ash[kc + 2][r] = pa[i].z;
            Ash[kc + 3][r] = pa[i].w;
            int kk = idx >> 5, c = (idx & 31) * 4;
            *(float4*)&Wsh[kk][c] = pw[i];
        }
        __syncthreads();

        if (kbi < 15) {
            int kb = (kbi + 1) * BK;
            #pragma unroll
            for (int i = 0; i < 2; i++) {
                int idx = tid * 2 + i;
                int r = idx >> 2, kc = (idx & 3) * 4;
                int row = row0 + r;
                int k = kb + kc;
                float4 v = make_float4(0.f, 0.f, 0.f, 0.f);
                if (row < nt) {
                    const float* src = (k < 128)
                        ? (g_mean + (size_t)row * H_ + k)
                        : (hin    + (size_t)row * H_ + (k - 128));
                    v = *(const float4*)src;
                }
                pa[i] = v;
                int kk = idx >> 5, c = (idx & 31) * 4;
                int kw = kb + kk;
                const float* ws = (kw < 128)
                    ? (Wl + (size_t)kw * H_ + c)
                    : (Wr + (size_t)(kw - 128) * H_ + c);
                pw[i] = *(const float4*)ws;
            }
        }

        #pragma unroll
        for (int kk = 0; kk < BK; kk++) {
            float4 a0 = *(const float4*)&Ash[kk][rm];
            float4 a1 = *(const float4*)&Ash[kk][rm + 64];
            float4 b0 = *(const float4*)&Wsh[kk][cn];
            float4 b1 = *(const float4*)&Wsh[kk][cn + 64];
            float a[8] = {a0.x, a0.y, a0.z, a0.w, a1.x, a1.y, a1.z, a1.w};
            float b[8] = {b0.x, b0.y, b0.z, b0.w, b1.x, b1.y, b1.z, b1.w};
            #pragma unroll
            for (int i = 0; i < 8; i++)
                #pragma unroll
                for (int j = 0; j < 8; j++)
                    acc[i][j] += a[i] * b[j];
        }
        __syncthreads();
    }

    // epilogue: bias add + store + per-column stat partials
    float4 bia0 = *(const float4*)&bb[cn];
    float4 bia1 = *(const float4*)&bb[cn + 64];
    float bias[8] = {bia0.x, bia0.y, bia0.z, bia0.w, bia1.x, bia1.y, bia1.z, bia1.w};
    float psum[8], psq[8];
    #pragma unroll
    for (int j = 0; j < 8; j++) { psum[j] = 0.f; psq[j] = 0.f; }
    #pragma unroll
    for (int i = 0; i < 8; i++) {
        int row = row0 + ((i < 4) ? (rm + i) : (64 + rm + i - 4));
        if (row < nt) {
            float v[8];
            #pragma unroll
            for (int j = 0; j < 8; j++) {
                v[j] = acc[i][j] + bias[j];
                psum[j] += v[j];
                psq[j]  += v[j] * v[j];
            }
            *(float4*)(g_bufB + (size_t)row * H_ + cn)      = make_float4(v[0], v[1], v[2], v[3]);
            *(float4*)(g_bufB + (size_t)row * H_ + cn + 64) = make_float4(v[4], v[5], v[6], v[7]);
        }
    }
    __syncthreads();   // done with Ash/Wsh as GEMM tiles
    #pragma unroll
    for (int j = 0; j < 4; j++) {
        Ash[ty][cn + j]      = psum[j];
        Wsh[ty][cn + j]      = psq[j];
    }
    __syncthreads();
    // cols 64..127 partials stored in second pass (same smem reused)
    __shared__ float As2[BK][64], Ws2[BK][64];
    #pragma unroll
    for (int j = 0; j < 4; j++) {
        As2[ty][cn + j - 0 + 0] = 0.f; // placeholder avoided below
    }
    // NOTE: instead of a second buffer dance, reduce cols 0..63 now:
    if (tid < 64) {
        float s = 0.f, q = 0.f;
        #pragma unroll
        for (int t = 0; t < 16; t++) { s += Ash[t][tid]; q += Wsh[t][tid]; }
        atomicAdd(&g_colsum[tid], s);
        atomicAdd(&g_colsumsq[tid], q);
    }
    // wait: cols 64..127 live at Ash[ty][64..127] too (cn+j covers 0..63 only since cn<64).
    // store them now:
    __syncthreads();
    #pragma unroll
    for (int j = 4; j < 8; j++) {
        Ash[ty][cn + 64 + j - 4] = psum[j];
        Wsh[ty][cn + 64 + j - 4] = psq[j];
    }
    __syncthreads();
    if (tid >= 64 && tid < 128) {
        int col = tid + 64; // 128..191? no:
        (void)col;
    }
    if (tid < 64) {
        float s = 0.f, q = 0.f;
        #pragma unroll
        for (int t = 0; t < 16; t++) { s += Ash[t][tid + 64]; q += Wsh[t][tid + 64]; }
        atomicAdd(&g_colsum[tid + 64], s);
        atomicAdd(&g_colsumsq[tid + 64], q);
    }
}

// BN apply + ReLU + score, mu/rstd/pnorm computed per warp from colsums
__global__ __launch_bounds__(256)
void bnscore_kernel(const float* __restrict__ gw, const float* __restrict__ be,
                    const float* __restrict__ p, int nt, float invnt) {
    int row = blockIdx.x * 8 + (threadIdx.x >> 5);
    int lane = threadIdx.x & 31;
    if (row >= nt) return;
    int c = lane * 4;
    float4 h  = *(const float4*)(g_bufB + (size_t)row * H_ + c);
    float4 cs = *(const float4*)&g_colsum[c];
    float4 cq = *(const float4*)&g_colsumsq[c];
    float4 gv = *(const float4*)&gw[c];
    float4 bv = *(const float4*)&be[c];
    float4 pv = *(const float4*)&p[c];
    float out[4], pp[4] = {pv.x, pv.y, pv.z, pv.w};
    float hh[4] = {h.x, h.y, h.z, h.w};
    float css[4] = {cs.x, cs.y, cs.z, cs.w};
    float cqq[4] = {cq.x, cq.y, cq.z, cq.w};
    float gg[4] = {gv.x, gv.y, gv.z, gv.w};
    float bbv[4] = {bv.x, bv.y, bv.z, bv.w};
    float dot = 0.f, pn = 0.f;
    #pragma unroll
    for (int j = 0; j < 4; j++) {
        float mu = css[j] * invnt;
        float var = cqq[j] * invnt - mu * mu;
        float r = rsqrtf(var + 1e-5f);
        float v = (hh[j] - mu) * r * gg[j] + bbv[j];
        v = fmaxf(v, 0.f);
        out[j] = v;
        dot += v * pp[j];
        pn  += pp[j] * pp[j];
    }
    *(float4*)(g_bufB + (size_t)row * H_ + c) = make_float4(out[0], out[1], out[2], out[3]);
    #pragma unroll
    for (int o = 16; o > 0; o >>= 1) {
        dot += __shfl_down_sync(0xffffffff, dot, o);
        pn  += __shfl_down_sync(0xffffffff, pn, o);
    }
    if (lane == 0) g_score[row] = dot * rsqrtf(pn);
}

// per-graph bitonic top-k (descending, tie-break smaller index first)
__global__ __launch_bounds__(512)
void topk_kernel(int ncur, int k, int epoch) {
    int gph = blockIdx.x;
    __shared__ float s[1024];
    __shared__ int   id[1024];
    for (int i = threadIdx.x; i < 1024; i += 512) {
        if (i < ncur) { s[i] = g_score[gph * ncur + i]; id[i] = i; }
        else          { s[i] = -FLT_MAX;                id[i] = 1024 + i; }
    }
    __syncthreads();
    for (int kk = 2; kk <= 1024; kk <<= 1) {
        for (int j = kk >> 1; j > 0; j >>= 1) {
            for (int i = threadIdx.x; i < 1024; i += 512) {
                int ixj = i ^ j;
                if (ixj > i) {
                    float si = s[i], sj = s[ixj];
                    int ii = id[i], ij = id[ixj];
                    bool less = (si < sj) || (si == sj && ii > ij);
                    bool up = ((i & kk) == 0);
                    if (less == up) {
                        s[i] = sj; s[ixj] = si;
                        id[i] = ij; id[ixj] = ii;
                    }
                }
            }
            __syncthreads();
        }
    }
    for (int r = threadIdx.x; r < k; r += 512) {
        int old = gph * ncur + id[r];
        int nw  = gph * k + r;
        g_perm[nw] = old;
        g_map[old] = (epoch << 16) | nw;
    }
}

// hp[new] = h[old] * tanh(score[old]); also resets counters for next block
__global__ __launch_bounds__(256)
void gather_kernel(int nnew, int ntn) {
    int nw = blockIdx.x * 8 + (threadIdx.x >> 5);
    int lane = threadIdx.x & 31;
    if (nw < nnew) {
        int old = g_perm[nw];
        float t = tanhf(g_score[old]);
        float4 v = *((const float4*)(g_bufB + (size_t)old * H_) + lane);
        v.x *= t; v.y *= t; v.z *= t; v.w *= t;
        *((float4*)(g_bufA + (size_t)nw * H_) + lane) = v;
    }
    // reset scratch for next block
    int gid = blockIdx.x * 256 + threadIdx.x;
    int tot = gridDim.x * 256;
    for (int i = gid; i < ntn; i += tot) { g_cnti[i] = 0; g_fill[i] = 0; }
    if (gid < H_ && ntn > 0) { g_colsum[gid] = 0.f; g_colsumsq[gid] = 0.f; }
}

// re-index edges + fused in-degree count for next block
__global__ void remap_kernel(const int* __restrict__ ei, int first, int epoch) {
    int e = blockIdx.x * blockDim.x + threadIdx.x;
    if (e >= EDGES) return;
    int s, d;
    if (first) { s = ei[e]; d = ei[EDGES + e]; }
    else       { s = g_src[e]; d = g_dst[e]; }
    int ns = -1, nd = -1;
    if (s >= 0) {
        int ms = g_map[s], md = g_map[d];
        if ((ms >> 16) == epoch && (md >> 16) == epoch) {
            ns = ms & 0xFFFF;
            nd = md & 0xFFFF;
            atomicAdd(&g_cnti[nd], 1);
        }
    }
    g_src[e] = ns;
    g_dst[e] = nd;
}

// per-graph [sum || max] readout, 4-way row split
__global__ __launch_bounds__(512)
void readout_kernel(int k, int off) {
    int gph = blockIdx.x;
    int rp = threadIdx.x >> 7;
    int j  = threadIdx.x & 127;
    const float* base = g_bufA + (size_t)gph * k * H_;
    float s = 0.f, m = -FLT_MAX;
    for (int r = rp; r < k; r += 4) {
        float v = base[(size_t)r * H_ + j];
        s += v;
        m = fmaxf(m, v);
    }
    __shared__ float ss[4][128], sm_[4][128];
    ss[rp][j] = s; sm_[rp][j] = m;
    __syncthreads();
    if (threadIdx.x < 128) {
        float fs = ss[0][j] + ss[1][j] + ss[2][j] + ss[3][j];
        float fm = fmaxf(fmaxf(sm_[0][j], sm_[1][j]), fmaxf(sm_[2][j], sm_[3][j]));
        g_flat[gph * 1024 + off + j]       = fs;
        g_flat[gph * 1024 + off + 128 + j] = fm;
    }
}

// hd = relu(flat @ Wd1 + bd1) : [32,1024]x[1024,512]
__global__ void dense1_kernel(const float* __restrict__ Wd1, const float* __restrict__ bd1) {
    int gph = blockIdx.x;
    int j = blockIdx.y * 256 + threadIdx.x;
    __shared__ float a[1024];
    for (int i = threadIdx.x; i < 1024; i += 256) a[i] = g_flat[gph * 1024 + i];
    __syncthreads();
    float acc = bd1[j];
    #pragma unroll 8
    for (int kk = 0; kk < 1024; kk++) acc += a[kk] * Wd1[kk * 512 + j];
    g_hd[gph * 512 + j] = fmaxf(acc, 0.f);
}

// out = hd @ Wd2 + bd2 : [32,512]x[512,10]
__global__ void dense2_kernel(const float* __restrict__ Wd2, const float* __restrict__ bd2,
                              float* __restrict__ out) {
    int gph = blockIdx.x;
    int c = threadIdx.x >> 5;
    int lane = threadIdx.x & 31;
    if (c >= 10) return;
    float acc = 0.f;
    for (int kk = lane; kk < 512; kk += 32) acc += g_hd[gph * 512 + kk] * Wd2[kk * 10 + c];
    #pragma unroll
    for (int o = 16; o > 0; o >>= 1) acc += __shfl_down_sync(0xffffffff, acc, o);
    if (lane == 0) out[gph * 10 + c] = acc + bd2[c];
}

// ---------------- launcher ----------------
extern "C" void kernel_launch(void* const* d_in, const int* in_sizes, int n_in,
                              void* d_out, int out_size) {
    const float* x  = (const float*)d_in[0];
    const int*   ei = (const int*)d_in[1];
    const float *Wl[4], *Wr[4], *bb[4], *gw[4], *be[4], *pp[4];
    int idx = 3;
    for (int b = 0; b < 4; b++) {
        Wl[b] = (const float*)d_in[idx++];
        Wr[b] = (const float*)d_in[idx++];
        bb[b] = (const float*)d_in[idx++];
        gw[b] = (const float*)d_in[idx++];
        be[b] = (const float*)d_in[idx++];
        pp[b] = (const float*)d_in[idx++];
    }
    const float* Wd1 = (const float*)d_in[27];
    const float* bd1 = (const float*)d_in[28];
    const float* Wd2 = (const float*)d_in[29];
    const float* bd2 = (const float*)d_in[30];
    float* out = (float*)d_out;

    prep_kernel<<<(NT_MAX + 255) / 256, 256>>>(G_ * N0);
    count_kernel<<<(EDGES + 255) / 256, 256>>>(ei);

    for (int b = 0; b < 4; b++) {
        int ncur = NCUR_H[b];
        int k    = KSEL_H[b];
        int nt   = G_ * ncur;
        int ntn  = (b < 3) ? G_ * KSEL_H[b] : 0;   // next block node count (= G*k)
        int first = (b == 0) ? 1 : 0;
        int epoch = b + 1;
        int nchunks = (nt + 1023) / 1024;

        scan_kernel<<<nchunks, 1024>>>(nt, nchunks);
        fill_kernel<<<(EDGES + 255) / 256, 256>>>(ei, first);
        gatheragg_kernel<<<(nt + 7) / 8, 256>>>(x, first, nt);
        gemm_kernel<<<(nt + 127) / 128, 256>>>(x, first, Wl[b], Wr[b], bb[b], nt);
        bnscore_kernel<<<(nt + 7) / 8, 256>>>(gw[b], be[b], pp[b], nt, 1.0f / (float)nt);
        topk_kernel<<<G_, 512>>>(ncur, k, epoch);
        gather_kernel<<<(G_ * k + 7) / 8, 256>>>(G_ * k, ntn);
        if (b < 3) remap_kernel<<<(EDGES + 255) / 256, 256>>>(ei, first, epoch);
        readout_kernel<<<G_, 512>>>(k, b * 256);
    }
    dense1_kernel<<<dim3(G_, 2), 256>>>(Wd1, bd1);
    dense2_kernel<<<G_, 320>>>(Wd2, bd2, out);
}

// round 4
// speedup vs baseline: 1.7070x; 1.0078x over previous
#include <cuda_runtime.h>
#include <math.h>
#include <float.h>

// ---------------- problem constants ----------------
#define G_      32
#define N0      1024
#define EDGES   524288          // 32 * 16384
#define H_      128
#define NT_MAX  32768           // 32 * 1024

static const int NCUR_H[4] = {1024, 820, 656, 525};
static const int KSEL_H[4] = {820, 656, 525, 420};

// fused-gemm shared memory layout (dynamic):
//   meanS : 128 x 132 floats  (mean tile, padded rows)
//   Wsh   : 2 x 16 x 128 floats (double-buffered weight tile)
//   Hsh   : 2 x 16 x 128 floats (double-buffered h_in tile, K-major)
#define SMEM_GEMM_BYTES ((128 * 132 + 2 * 16 * 128 + 2 * 16 * 128) * 4)

// ---------------- device scratch (static, no allocation) ----------------
__device__ __align__(16) float g_bufA[NT_MAX * H_];    // h_in for blocks >=2 ; hp output of pooling
__device__ __align__(16) float g_bufB[NT_MAX * H_];    // conv output -> BN'd h
__device__ int   g_cnti[NT_MAX];         // in-degree
__device__ int   g_off [NT_MAX];         // local exclusive offsets (within 1024-chunk)
__device__ int   g_fill[NT_MAX];         // fill cursors
__device__ int   g_bsum[32];             // per-chunk totals
__device__ int   g_bpre[32];             // chunk prefix
__device__ int   g_tick;                 // scan ticket (self-resetting)
__device__ int   g_csr [EDGES];          // src ids grouped by dst
__device__ int   g_src [EDGES];
__device__ int   g_dst [EDGES];
__device__ float g_score[NT_MAX];
__device__ int   g_map [NT_MAX];         // (epoch<<16) | new_id
__device__ int   g_perm[NT_MAX];
__device__ __align__(16) float g_colsum[H_];
__device__ __align__(16) float g_colsumsq[H_];
__device__ float g_flat[G_ * 1024];      // [G, 8H]
__device__ float g_hd  [G_ * 512];       // [G, 4H]

// ---------------- kernels ----------------

// block-0 only: zero counters & colsums
__global__ void prep_kernel(int nt) {
    int i = blockIdx.x * blockDim.x + threadIdx.x;
    if (i < nt) { g_cnti[i] = 0; g_fill[i] = 0; }
    if (i < H_) { g_colsum[i] = 0.f; g_colsumsq[i] = 0.f; }
}

// block-0 only: in-degree histogram from input edges (all valid)
__global__ void count_kernel(const int* __restrict__ ei) {
    int e = blockIdx.x * blockDim.x + threadIdx.x;
    if (e >= EDGES) return;
    atomicAdd(&g_cnti[ei[EDGES + e]], 1);
}

// warp-shuffle scan per 1024-chunk + decoupled level-2 prefix
__global__ __launch_bounds__(1024)
void scan_kernel(int nt, int nblk) {
    __shared__ int wsum[32];
    __shared__ int btot;
    int tid = threadIdx.x;
    int i = blockIdx.x * 1024 + tid;
    int lane = tid & 31, wid = tid >> 5;
    int v = (i < nt) ? g_cnti[i] : 0;
    int inc = v;
    #pragma unroll
    for (int o = 1; o < 32; o <<= 1) {
        int t = __shfl_up_sync(0xffffffff, inc, o);
        if (lane >= o) inc += t;
    }
    if (lane == 31) wsum[wid] = inc;
    __syncthreads();
    if (wid == 0) {
        int ws = wsum[lane];
        int wi = ws;
        #pragma unroll
        for (int o = 1; o < 32; o <<= 1) {
            int t = __shfl_up_sync(0xffffffff, wi, o);
            if (lane >= o) wi += t;
        }
        wsum[lane] = wi - ws;           // exclusive warp prefix
        if (lane == 31) btot = wi;      // block total
    }
    __syncthreads();
    if (i < nt) g_off[i] = wsum[wid] + inc - v;
    if (tid == 0) {
        g_bsum[blockIdx.x] = btot;
        __threadfence();
        int t = atomicAdd(&g_tick, 1);
        if (t == nblk - 1) {
            volatile int* vb = g_bsum;
            int acc = 0;
            for (int b = 0; b < nblk; b++) { g_bpre[b] = acc; acc += vb[b]; }
            g_tick = 0;
        }
    }
}

// scatter edge src ids into CSR slots of their dst
__global__ void fill_kernel(const int* __restrict__ ei, int first) {
    int e = blockIdx.x * blockDim.x + threadIdx.x;
    if (e >= EDGES) return;
    int s, d;
    if (first) { s = ei[e]; d = ei[EDGES + e]; }
    else       { s = g_src[e]; d = g_dst[e]; }
    if (s < 0) return;
    int pos = atomicAdd(&g_fill[d], 1);
    g_csr[g_off[d] + g_bpre[d >> 10] + pos] = s;
}

// ================= fused gather-mean + GEMM + BN-stats =================
// Phase 1: each warp computes mean rows for its 16 tile rows -> smem meanS
// Phase 2: h = [mean || h_in] @ [Wl;Wr] + bb  (128x128 tile, BK=16, dbl-buf)
// Epilogue: store h, accumulate per-column sum/sumsq atomics.
__global__ __launch_bounds__(256, 2)
void gemm_kernel(const float* __restrict__ x, int first,
                 const float* __restrict__ Wl, const float* __restrict__ Wr,
                 const float* __restrict__ bb, int nt) {
    extern __shared__ float smem[];
    float* meanS = smem;                        // [128][132]
    float* WshB  = smem + 128 * 132;            // [2][16][128]
    float* HshB  = WshB + 2 * 16 * 128;         // [2][16][128]
    #define WSH(b,k,c) WshB[(b) * 2048 + (k) * 128 + (c)]
    #define HSH(b,k,m) HshB[(b) * 2048 + (k) * 128 + (m)]

    const float* hin = first ? x : g_bufA;
    int row0 = blockIdx.x * 128;
    int tid = threadIdx.x;
    int w = tid >> 5, lane = tid & 31;
    int tx = tid & 15, ty = tid >> 4;
    int rm = ty * 4, cn = tx * 4;

    // ---- prefetch W block 0 (hidden behind gather) ----
    float4 pw[2];
    #pragma unroll
    for (int i = 0; i < 2; i++) {
        int idx = tid * 2 + i;
        int kk = idx >> 5, c = (idx & 31) * 4;
        pw[i] = *(const float4*)(Wl + (size_t)kk * H_ + c);
    }

    // ---- phase 1: gather mean for rows [row0, row0+128) ----
    for (int i = 0; i < 16; i++) {
        int rl = w * 16 + i;
        int row = row0 + rl;
        float4 acc = make_float4(0.f, 0.f, 0.f, 0.f);
        if (row < nt) {
            int deg  = g_cnti[row];
            int base = g_off[row] + g_bpre[row >> 10];
            int j = 0;
            for (; j + 4 <= deg; j += 4) {
                int s0 = g_csr[base + j];
                int s1 = g_csr[base + j + 1];
                int s2 = g_csr[base + j + 2];
                int s3 = g_csr[base + j + 3];
                float4 a = *((const float4*)(hin + (size_t)s0 * H_) + lane);
                float4 b = *((const float4*)(hin + (size_t)s1 * H_) + lane);
                float4 c = *((const float4*)(hin + (size_t)s2 * H_) + lane);
                float4 d = *((const float4*)(hin + (size_t)s3 * H_) + lane);
                acc.x += a.x + b.x + c.x + d.x;
                acc.y += a.y + b.y + c.y + d.y;
                acc.z += a.z + b.z + c.z + d.z;
                acc.w += a.w + b.w + c.w + d.w;
            }
            for (; j < deg; j++) {
                int s0 = g_csr[base + j];
                float4 a = *((const float4*)(hin + (size_t)s0 * H_) + lane);
                acc.x += a.x; acc.y += a.y; acc.z += a.z; acc.w += a.w;
            }
            float inv = 1.0f / fmaxf((float)deg, 1.0f);
            acc.x *= inv; acc.y *= inv; acc.z *= inv; acc.w *= inv;
        }
        *(float4*)&meanS[rl * 132 + lane * 4] = acc;
    }

    // store W block 0
    #pragma unroll
    for (int i = 0; i < 2; i++) {
        int idx = tid * 2 + i;
        int kk = idx >> 5, c = (idx & 31) * 4;
        *(float4*)&WSH(0, kk, c) = pw[i];
    }
    __syncthreads();

    float acc[8][8];
    #pragma unroll
    for (int i = 0; i < 8; i++)
        #pragma unroll
        for (int j = 0; j < 8; j++) acc[i][j] = 0.f;

    int cur = 0;
    float4 ph[2];

    // ---- first half: k = 0..127, A from meanS ----
    for (int kbi = 0; kbi < 8; kbi++) {
        // prefetch next W (always exists: blocks 1..8)
        int kwb = (kbi + 1) * 16;
        #pragma unroll
        for (int i = 0; i < 2; i++) {
            int idx = tid * 2 + i;
            int kk = idx >> 5, c = (idx & 31) * 4;
            int kw = kwb + kk;
            const float* ws = (kw < 128) ? (Wl + (size_t)kw * H_ + c)
                                         : (Wr + (size_t)(kw - 128) * H_ + c);
            pw[i] = *(const float4*)ws;
        }
        if (kbi == 7) {
            // prefetch H block 0 (hin cols 0..15)
            #pragma unroll
            for (int i = 0; i < 2; i++) {
                int idx = tid * 2 + i;
                int r = idx >> 2, kc = (idx & 3) * 4;
                int row = row0 + r;
                ph[i] = (row < nt) ? *(const float4*)(hin + (size_t)row * H_ + kc)
                                   : make_float4(0.f, 0.f, 0.f, 0.f);
            }
        }
        // compute
        int kb = kbi * 16;
        #pragma unroll
        for (int kk = 0; kk < 16; kk++) {
            int kcol = kb + kk;
            float a[8];
            #pragma unroll
            for (int i = 0; i < 4; i++) {
                a[i]     = meanS[(rm + i) * 132 + kcol];
                a[4 + i] = meanS[(rm + 64 + i) * 132 + kcol];
            }
            float4 b0 = *(const float4*)&WSH(cur, kk, cn);
            float4 b1 = *(const float4*)&WSH(cur, kk, cn + 64);
            float b[8] = {b0.x, b0.y, b0.z, b0.w, b1.x, b1.y, b1.z, b1.w};
            #pragma unroll
            for (int i = 0; i < 8; i++)
                #pragma unroll
                for (int j = 0; j < 8; j++)
                    acc[i][j] += a[i] * b[j];
        }
        // store prefetched into other buffer
        #pragma unroll
        for (int i = 0; i < 2; i++) {
            int idx = tid * 2 + i;
            int kk = idx >> 5, c = (idx & 31) * 4;
            *(float4*)&WSH(cur ^ 1, kk, c) = pw[i];
        }
        if (kbi == 7) {
            #pragma unroll
            for (int i = 0; i < 2; i++) {
                int idx = tid * 2 + i;
                int r = idx >> 2, kc = (idx & 3) * 4;
                HSH(cur ^ 1, kc + 0, r) = ph[i].x;
                HSH(cur ^ 1, kc + 1, r) = ph[i].y;
                HSH(cur ^ 1, kc + 2, r) = ph[i].z;
                HSH(cur ^ 1, kc + 3, r) = ph[i].w;
            }
        }
        __syncthreads();
        cur ^= 1;
    }

    // ---- second half: k = 128..255, A from Hsh ----
    for (int kbi = 8; kbi < 16; kbi++) {
        if (kbi < 15) {
            int kwb = (kbi + 1) * 16;     // >= 144 -> Wr
            int hb  = (kbi + 1 - 8) * 16; // hin col base
            #pragma unroll
            for (int i = 0; i < 2; i++) {
                int idx = tid * 2 + i;
                int kk = idx >> 5, c = (idx & 31) * 4;
                pw[i] = *(const float4*)(Wr + (size_t)(kwb + kk - 128) * H_ + c);
                int r = idx >> 2, kc = (idx & 3) * 4;
                int row = row0 + r;
                ph[i] = (row < nt) ? *(const float4*)(hin + (size_t)row * H_ + hb + kc)
                                   : make_float4(0.f, 0.f, 0.f, 0.f);
            }
        }
        #pragma unroll
        for (int kk = 0; kk < 16; kk++) {
            float4 a0 = *(const float4*)&HSH(cur, kk, rm);
            float4 a1 = *(const float4*)&HSH(cur, kk, rm + 64);
            float4 b0 = *(const float4*)&WSH(cur, kk, cn);
            float4 b1 = *(const float4*)&WSH(cur, kk, cn + 64);
            float a[8] = {a0.x, a0.y, a0.z, a0.w, a1.x, a1.y, a1.z, a1.w};
            float b[8] = {b0.x, b0.y, b0.z, b0.w, b1.x, b1.y, b1.z, b1.w};
            #pragma unroll
            for (int i = 0; i < 8; i++)
                #pragma unroll
                for (int j = 0; j < 8; j++)
                    acc[i][j] += a[i] * b[j];
        }
        if (kbi < 15) {
            #pragma unroll
            for (int i = 0; i < 2; i++) {
                int idx = tid * 2 + i;
                int kk = idx >> 5, c = (idx & 31) * 4;
                *(float4*)&WSH(cur ^ 1, kk, c) = pw[i];
                int r = idx >> 2, kc = (idx & 3) * 4;
                HSH(cur ^ 1, kc + 0, r) = ph[i].x;
                HSH(cur ^ 1, kc + 1, r) = ph[i].y;
                HSH(cur ^ 1, kc + 2, r) = ph[i].z;
                HSH(cur ^ 1, kc + 3, r) = ph[i].w;
            }
        }
        __syncthreads();
        cur ^= 1;
    }

    // ---- epilogue: bias + store + column-stat partials ----
    float4 bia0 = *(const float4*)&bb[cn];
    float4 bia1 = *(const float4*)&bb[cn + 64];
    float bias[8] = {bia0.x, bia0.y, bia0.z, bia0.w, bia1.x, bia1.y, bia1.z, bia1.w};
    float psum[8], psq[8];
    #pragma unroll
    for (int j = 0; j < 8; j++) { psum[j] = 0.f; psq[j] = 0.f; }
    #pragma unroll
    for (int i = 0; i < 8; i++) {
        int row = row0 + ((i < 4) ? (rm + i) : (64 + rm + i - 4));
        if (row < nt) {
            float v[8];
            #pragma unroll
            for (int j = 0; j < 8; j++) {
                v[j] = acc[i][j] + bias[j];
                psum[j] += v[j];
                psq[j]  += v[j] * v[j];
            }
            *(float4*)(g_bufB + (size_t)row * H_ + cn)      = make_float4(v[0], v[1], v[2], v[3]);
            *(float4*)(g_bufB + (size_t)row * H_ + cn + 64) = make_float4(v[4], v[5], v[6], v[7]);
        }
    }
    // reduce stat partials through smem (reuse meanS region)
    float* sumS = meanS;          // [16][128]
    float* sqS  = meanS + 2048;   // [16][128]
    #pragma unroll
    for (int j = 0; j < 4; j++) {
        sumS[ty * 128 + cn + j]      = psum[j];
        sumS[ty * 128 + cn + 64 + j] = psum[4 + j];
        sqS [ty * 128 + cn + j]      = psq[j];
        sqS [ty * 128 + cn + 64 + j] = psq[4 + j];
    }
    __syncthreads();
    if (tid < 128) {
        float s = 0.f, q = 0.f;
        #pragma unroll
        for (int t = 0; t < 16; t++) {
            s += sumS[t * 128 + tid];
            q += sqS [t * 128 + tid];
        }
        atomicAdd(&g_colsum[tid], s);
        atomicAdd(&g_colsumsq[tid], q);
    }
    #undef WSH
    #undef HSH
}

// BN apply + ReLU + score, mu/rstd/pnorm computed per warp from colsums
__global__ __launch_bounds__(256)
void bnscore_kernel(const float* __restrict__ gw, const float* __restrict__ be,
                    const float* __restrict__ p, int nt, float invnt) {
    int row = blockIdx.x * 8 + (threadIdx.x >> 5);
    int lane = threadIdx.x & 31;
    if (row >= nt) return;
    int c = lane * 4;
    float4 h  = *(const float4*)(g_bufB + (size_t)row * H_ + c);
    float4 cs = *(const float4*)&g_colsum[c];
    float4 cq = *(const float4*)&g_colsumsq[c];
    float4 gv = *(const float4*)&gw[c];
    float4 bv = *(const float4*)&be[c];
    float4 pv = *(const float4*)&p[c];
    float out[4], pp[4] = {pv.x, pv.y, pv.z, pv.w};
    float hh[4] = {h.x, h.y, h.z, h.w};
    float css[4] = {cs.x, cs.y, cs.z, cs.w};
    float cqq[4] = {cq.x, cq.y, cq.z, cq.w};
    float gg[4] = {gv.x, gv.y, gv.z, gv.w};
    float bbv[4] = {bv.x, bv.y, bv.z, bv.w};
    float dot = 0.f, pn = 0.f;
    #pragma unroll
    for (int j = 0; j < 4; j++) {
        float mu = css[j] * invnt;
        float var = cqq[j] * invnt - mu * mu;
        float r = rsqrtf(var + 1e-5f);
        float v = (hh[j] - mu) * r * gg[j] + bbv[j];
        v = fmaxf(v, 0.f);
        out[j] = v;
        dot += v * pp[j];
        pn  += pp[j] * pp[j];
    }
    *(float4*)(g_bufB + (size_t)row * H_ + c) = make_float4(out[0], out[1], out[2], out[3]);
    #pragma unroll
    for (int o = 16; o > 0; o >>= 1) {
        dot += __shfl_down_sync(0xffffffff, dot, o);
        pn  += __shfl_down_sync(0xffffffff, pn, o);
    }
    if (lane == 0) g_score[row] = dot * rsqrtf(pn);
}

// per-graph bitonic top-k (descending, tie-break smaller index first)
__global__ __launch_bounds__(512)
void topk_kernel(int ncur, int k, int epoch) {
    int gph = blockIdx.x;
    __shared__ float s[1024];
    __shared__ int   id[1024];
    for (int i = threadIdx.x; i < 1024; i += 512) {
        if (i < ncur) { s[i] = g_score[gph * ncur + i]; id[i] = i; }
        else          { s[i] = -FLT_MAX;                id[i] = 1024 + i; }
    }
    __syncthreads();
    for (int kk = 2; kk <= 1024; kk <<= 1) {
        for (int j = kk >> 1; j > 0; j >>= 1) {
            for (int i = threadIdx.x; i < 1024; i += 512) {
                int ixj = i ^ j;
                if (ixj > i) {
                    float si = s[i], sj = s[ixj];
                    int ii = id[i], ij = id[ixj];
                    bool less = (si < sj) || (si == sj && ii > ij);
                    bool up = ((i & kk) == 0);
                    if (less == up) {
                        s[i] = sj; s[ixj] = si;
                        id[i] = ij; id[ixj] = ii;
                    }
                }
            }
            __syncthreads();
        }
    }
    for (int r = threadIdx.x; r < k; r += 512) {
        int old = gph * ncur + id[r];
        int nw  = gph * k + r;
        g_perm[nw] = old;
        g_map[old] = (epoch << 16) | nw;
    }
}

// hp[new] = h[old] * tanh(score[old]); also resets counters for next block
__global__ __launch_bounds__(256)
void gather_kernel(int nnew, int ntn) {
    int nw = blockIdx.x * 8 + (threadIdx.x >> 5);
    int lane = threadIdx.x & 31;
    if (nw < nnew) {
        int old = g_perm[nw];
        float t = tanhf(g_score[old]);
        float4 v = *((const float4*)(g_bufB + (size_t)old * H_) + lane);
        v.x *= t; v.y *= t; v.z *= t; v.w *= t;
        *((float4*)(g_bufA + (size_t)nw * H_) + lane) = v;
    }
    int gid = blockIdx.x * 256 + threadIdx.x;
    int tot = gridDim.x * 256;
    for (int i = gid; i < ntn; i += tot) { g_cnti[i] = 0; g_fill[i] = 0; }
    if (gid < H_ && ntn > 0) { g_colsum[gid] = 0.f; g_colsumsq[gid] = 0.f; }
}

// re-index edges + fused in-degree count for next block
__global__ void remap_kernel(const int* __restrict__ ei, int first, int epoch) {
    int e = blockIdx.x * blockDim.x + threadIdx.x;
    if (e >= EDGES) return;
    int s, d;
    if (first) { s = ei[e]; d = ei[EDGES + e]; }
    else       { s = g_src[e]; d = g_dst[e]; }
    int ns = -1, nd = -1;
    if (s >= 0) {
        int ms = g_map[s], md = g_map[d];
        if ((ms >> 16) == epoch && (md >> 16) == epoch) {
            ns = ms & 0xFFFF;
            nd = md & 0xFFFF;
            atomicAdd(&g_cnti[nd], 1);
        }
    }
    g_src[e] = ns;
    g_dst[e] = nd;
}

// per-graph [sum || max] readout, 4-way row split
__global__ __launch_bounds__(512)
void readout_kernel(int k, int off) {
    int gph = blockIdx.x;
    int rp = threadIdx.x >> 7;
    int j  = threadIdx.x & 127;
    const float* base = g_bufA + (size_t)gph * k * H_;
    float s = 0.f, m = -FLT_MAX;
    for (int r = rp; r < k; r += 4) {
        float v = base[(size_t)r * H_ + j];
        s += v;
        m = fmaxf(m, v);
    }
    __shared__ float ss[4][128], sm_[4][128];
    ss[rp][j] = s; sm_[rp][j] = m;
    __syncthreads();
    if (threadIdx.x < 128) {
        float fs = ss[0][j] + ss[1][j] + ss[2][j] + ss[3][j];
        float fm = fmaxf(fmaxf(sm_[0][j], sm_[1][j]), fmaxf(sm_[2][j], sm_[3][j]));
        g_flat[gph * 1024 + off + j]       = fs;
        g_flat[gph * 1024 + off + 128 + j] = fm;
    }
}

// hd = relu(flat @ Wd1 + bd1) : [32,1024]x[1024,512]
__global__ void dense1_kernel(const float* __restrict__ Wd1, const float* __restrict__ bd1) {
    int gph = blockIdx.x;
    int j = blockIdx.y * 256 + threadIdx.x;
    __shared__ float a[1024];
    for (int i = threadIdx.x; i < 1024; i += 256) a[i] = g_flat[gph * 1024 + i];
    __syncthreads();
    float acc = bd1[j];
    #pragma unroll 8
    for (int kk = 0; kk < 1024; kk++) acc += a[kk] * Wd1[kk * 512 + j];
    g_hd[gph * 512 + j] = fmaxf(acc, 0.f);
}

// out = hd @ Wd2 + bd2 : [32,512]x[512,10]
__global__ void dense2_kernel(const float* __restrict__ Wd2, const float* __restrict__ bd2,
                              float* __restrict__ out) {
    int gph = blockIdx.x;
    int c = threadIdx.x >> 5;
    int lane = threadIdx.x & 31;
    if (c >= 10) return;
    float acc = 0.f;
    for (int kk = lane; kk < 512; kk += 32) acc += g_hd[gph * 512 + kk] * Wd2[kk * 10 + c];
    #pragma unroll
    for (int o = 16; o > 0; o >>= 1) acc += __shfl_down_sync(0xffffffff, acc, o);
    if (lane == 0) out[gph * 10 + c] = acc + bd2[c];
}

// ---------------- launcher ----------------
extern "C" void kernel_launch(void* const* d_in, const int* in_sizes, int n_in,
                              void* d_out, int out_size) {
    const float* x  = (const float*)d_in[0];
    const int*   ei = (const int*)d_in[1];
    const float *Wl[4], *Wr[4], *bb[4], *gw[4], *be[4], *pp[4];
    int idx = 3;
    for (int b = 0; b < 4; b++) {
        Wl[b] = (const float*)d_in[idx++];
        Wr[b] = (const float*)d_in[idx++];
        bb[b] = (const float*)d_in[idx++];
        gw[b] = (const float*)d_in[idx++];
        be[b] = (const float*)d_in[idx++];
        pp[b] = (const float*)d_in[idx++];
    }
    const float* Wd1 = (const float*)d_in[27];
    const float* bd1 = (const float*)d_in[28];
    const float* Wd2 = (const float*)d_in[29];
    const float* bd2 = (const float*)d_in[30];
    float* out = (float*)d_out;

    cudaFuncSetAttribute(gemm_kernel, cudaFuncAttributeMaxDynamicSharedMemorySize,
                         SMEM_GEMM_BYTES);

    prep_kernel<<<(NT_MAX + 255) / 256, 256>>>(G_ * N0);
    count_kernel<<<(EDGES + 255) / 256, 256>>>(ei);

    for (int b = 0; b < 4; b++) {
        int ncur = NCUR_H[b];
        int k    = KSEL_H[b];
        int nt   = G_ * ncur;
        int ntn  = (b < 3) ? G_ * KSEL_H[b] : 0;
        int first = (b == 0) ? 1 : 0;
        int epoch = b + 1;
        int nchunks = (nt + 1023) / 1024;

        scan_kernel<<<nchunks, 1024>>>(nt, nchunks);
        fill_kernel<<<(EDGES + 255) / 256, 256>>>(ei, first);
        gemm_kernel<<<(nt + 127) / 128, 256, SMEM_GEMM_BYTES>>>(x, first, Wl[b], Wr[b], bb[b], nt);
        bnscore_kernel<<<(nt + 7) / 8, 256>>>(gw[b], be[b], pp[b], nt, 1.0f / (float)nt);
        topk_kernel<<<G_, 512>>>(ncur, k, epoch);
        gather_kernel<<<(G_ * k + 7) / 8, 256>>>(G_ * k, ntn);
        if (b < 3) remap_kernel<<<(EDGES + 255) / 256, 256>>>(ei, first, epoch);
        readout_kernel<<<G_, 512>>>(k, b * 256);
    }
    dense1_kernel<<<dim3(G_, 2), 256>>>(Wd1, bd1);
    dense2_kernel<<<G_, 320>>>(Wd2, bd2, out);
}

// round 5
// speedup vs baseline: 1.9293x; 1.1303x over previous
#include <cuda_runtime.h>
#include <math.h>
#include <float.h>

// ---------------- problem constants ----------------
#define G_      32
#define EPG     16384                 // edges per graph
#define EDGES   (G_ * EPG)
#define H_      128
#define NT_MAX  32768

static const int NCUR_H[4] = {1024, 820, 656, 525};
static const int KSEL_H[4] = {820, 656, 525, 420};

// fused-gemm shared memory (dynamic)
#define SMEM_GEMM_BYTES ((128 * 132 + 2 * 16 * 128 + 2 * 16 * 128) * 4)
// mega kernel shared memory (dynamic): 5 * 4KB arrays + 32KB readout reduce
#define MEGA_SMEM (5 * 4096 + 32 * 128 * 2 * 4)

// ---------------- device scratch ----------------
__device__ __align__(16) float g_bufA[NT_MAX * H_];  // pooled h (input of next block)
__device__ __align__(16) float g_bufB[NT_MAX * H_];  // conv out -> BN'd h
__device__ int   g_cnti[NT_MAX];       // in-degree
__device__ int   g_off [NT_MAX];       // ABSOLUTE csr base per node
__device__ int   g_csr [EDGES];        // neighbor global row ids grouped by dst
__device__ int   g_srcL[EDGES];        // graph-local remapped src (-1 invalid)
__device__ int   g_dstL[EDGES];
__device__ __align__(16) float g_colsum[4 * H_];   // per-block slots
__device__ __align__(16) float g_colsq [4 * H_];
__device__ float g_flat[G_ * 1024];    // [G, 8H]

// ---------------- csr0: per-graph count+scan+fill for input edges ----------------
__global__ __launch_bounds__(1024)
void csr0_kernel(const int* __restrict__ ei) {
    __shared__ int cnt[1024], off[1024], cur[1024];
    __shared__ int wsum[32];
    int g = blockIdx.x, tid = threadIdx.x;
    int lane = tid & 31, wid = tid >> 5;
    cnt[tid] = 0;
    __syncthreads();
    const int* srcp = ei + g * EPG;
    const int* dstp = ei + EDGES + g * EPG;
    for (int e = tid; e < EPG; e += 1024)
        atomicAdd(&cnt[dstp[e] - (g << 10)], 1);
    __syncthreads();
    // block exclusive scan of cnt
    int v = cnt[tid];
    int inc = v;
    #pragma unroll
    for (int o = 1; o < 32; o <<= 1) {
        int t = __shfl_up_sync(0xffffffffu, inc, o);
        if (lane >= o) inc += t;
    }
    if (lane == 31) wsum[wid] = inc;
    __syncthreads();
    if (wid == 0) {
        int ws = wsum[lane], wi = ws;
        #pragma unroll
        for (int o = 1; o < 32; o <<= 1) {
            int t = __shfl_up_sync(0xffffffffu, wi, o);
            if (lane >= o) wi += t;
        }
        wsum[lane] = wi - ws;
    }
    __syncthreads();
    int ex = wsum[wid] + inc - v;
    off[tid] = ex;
    g_off [g * 1024 + tid] = g * EPG + ex;
    g_cnti[g * 1024 + tid] = v;
    cur[tid] = 0;
    __syncthreads();
    for (int e = tid; e < EPG; e += 1024) {
        int s = srcp[e];                    // global row id
        int d = dstp[e] - (g << 10);
        int pos = atomicAdd(&cur[d], 1);
        g_csr[g * EPG + off[d] + pos] = s;
    }
    if (g == 0 && tid < 4 * H_) { g_colsum[tid] = 0.f; g_colsq[tid] = 0.f; }
}

// ---------------- fused gather-mean + GEMM + BN-stats ----------------
__global__ __launch_bounds__(256, 2)
void gemm_kernel(const float* __restrict__ x, int first, int slot,
                 const float* __restrict__ Wl, const float* __restrict__ Wr,
                 const float* __restrict__ bb, int nt) {
    extern __shared__ float smem[];
    float* meanS = smem;                        // [128][132]
    float* WshB  = smem + 128 * 132;            // [2][16][128]
    float* HshB  = WshB + 2 * 16 * 128;         // [2][16][128]
    #define WSH(b,k,c) WshB[(b) * 2048 + (k) * 128 + (c)]
    #define HSH(b,k,m) HshB[(b) * 2048 + (k) * 128 + (m)]

    const float* hin = first ? x : g_bufA;
    int row0 = blockIdx.x * 128;
    int tid = threadIdx.x;
    int w = tid >> 5, lane = tid & 31;
    int tx = tid & 15, ty = tid >> 4;
    int rm = ty * 4, cn = tx * 4;

    float4 pw[2];
    #pragma unroll
    for (int i = 0; i < 2; i++) {
        int idx = tid * 2 + i;
        int kk = idx >> 5, c = (idx & 31) * 4;
        pw[i] = *(const float4*)(Wl + (size_t)kk * H_ + c);
    }

    // phase 1: gather means into smem
    for (int i = 0; i < 16; i++) {
        int rl = w * 16 + i;
        int row = row0 + rl;
        float4 acc = make_float4(0.f, 0.f, 0.f, 0.f);
        if (row < nt) {
            int deg  = g_cnti[row];
            int base = g_off[row];
            int j = 0;
            for (; j + 4 <= deg; j += 4) {
                int s0 = g_csr[base + j];
                int s1 = g_csr[base + j + 1];
                int s2 = g_csr[base + j + 2];
                int s3 = g_csr[base + j + 3];
                float4 a = *((const float4*)(hin + (size_t)s0 * H_) + lane);
                float4 b = *((const float4*)(hin + (size_t)s1 * H_) + lane);
                float4 c = *((const float4*)(hin + (size_t)s2 * H_) + lane);
                float4 d = *((const float4*)(hin + (size_t)s3 * H_) + lane);
                acc.x += a.x + b.x + c.x + d.x;
                acc.y += a.y + b.y + c.y + d.y;
                acc.z += a.z + b.z + c.z + d.z;
                acc.w += a.w + b.w + c.w + d.w;
            }
            for (; j < deg; j++) {
                int s0 = g_csr[base + j];
                float4 a = *((const float4*)(hin + (size_t)s0 * H_) + lane);
                acc.x += a.x; acc.y += a.y; acc.z += a.z; acc.w += a.w;
            }
            float inv = 1.0f / fmaxf((float)deg, 1.0f);
            acc.x *= inv; acc.y *= inv; acc.z *= inv; acc.w *= inv;
        }
        *(float4*)&meanS[rl * 132 + lane * 4] = acc;
    }
    #pragma unroll
    for (int i = 0; i < 2; i++) {
        int idx = tid * 2 + i;
        int kk = idx >> 5, c = (idx & 31) * 4;
        *(float4*)&WSH(0, kk, c) = pw[i];
    }
    __syncthreads();

    float acc[8][8];
    #pragma unroll
    for (int i = 0; i < 8; i++)
        #pragma unroll
        for (int j = 0; j < 8; j++) acc[i][j] = 0.f;

    int cur = 0;
    float4 ph[2];

    for (int kbi = 0; kbi < 8; kbi++) {
        int kwb = (kbi + 1) * 16;
        #pragma unroll
        for (int i = 0; i < 2; i++) {
            int idx = tid * 2 + i;
            int kk = idx >> 5, c = (idx & 31) * 4;
            int kw = kwb + kk;
            const float* ws = (kw < 128) ? (Wl + (size_t)kw * H_ + c)
                                         : (Wr + (size_t)(kw - 128) * H_ + c);
            pw[i] = *(const float4*)ws;
        }
        if (kbi == 7) {
            #pragma unroll
            for (int i = 0; i < 2; i++) {
                int idx = tid * 2 + i;
                int r = idx >> 2, kc = (idx & 3) * 4;
                int row = row0 + r;
                ph[i] = (row < nt) ? *(const float4*)(hin + (size_t)row * H_ + kc)
                                   : make_float4(0.f, 0.f, 0.f, 0.f);
            }
        }
        int kb = kbi * 16;
        #pragma unroll
        for (int kk = 0; kk < 16; kk++) {
            int kcol = kb + kk;
            float a[8];
            #pragma unroll
            for (int i = 0; i < 4; i++) {
                a[i]     = meanS[(rm + i) * 132 + kcol];
                a[4 + i] = meanS[(rm + 64 + i) * 132 + kcol];
            }
            float4 b0 = *(const float4*)&WSH(cur, kk, cn);
            float4 b1 = *(const float4*)&WSH(cur, kk, cn + 64);
            float b[8] = {b0.x, b0.y, b0.z, b0.w, b1.x, b1.y, b1.z, b1.w};
            #pragma unroll
            for (int i = 0; i < 8; i++)
                #pragma unroll
                for (int j = 0; j < 8; j++)
                    acc[i][j] += a[i] * b[j];
        }
        #pragma unroll
        for (int i = 0; i < 2; i++) {
            int idx = tid * 2 + i;
            int kk = idx >> 5, c = (idx & 31) * 4;
            *(float4*)&WSH(cur ^ 1, kk, c) = pw[i];
        }
        if (kbi == 7) {
            #pragma unroll
            for (int i = 0; i < 2; i++) {
                int idx = tid * 2 + i;
                int r = idx >> 2, kc = (idx & 3) * 4;
                HSH(cur ^ 1, kc + 0, r) = ph[i].x;
                HSH(cur ^ 1, kc + 1, r) = ph[i].y;
                HSH(cur ^ 1, kc + 2, r) = ph[i].z;
                HSH(cur ^ 1, kc + 3, r) = ph[i].w;
            }
        }
        __syncthreads();
        cur ^= 1;
    }

    for (int kbi = 8; kbi < 16; kbi++) {
        if (kbi < 15) {
            int kwb = (kbi + 1) * 16;
            int hb  = (kbi + 1 - 8) * 16;
            #pragma unroll
            for (int i = 0; i < 2; i++) {
                int idx = tid * 2 + i;
                int kk = idx >> 5, c = (idx & 31) * 4;
                pw[i] = *(const float4*)(Wr + (size_t)(kwb + kk - 128) * H_ + c);
                int r = idx >> 2, kc = (idx & 3) * 4;
                int row = row0 + r;
                ph[i] = (row < nt) ? *(const float4*)(hin + (size_t)row * H_ + hb + kc)
                                   : make_float4(0.f, 0.f, 0.f, 0.f);
            }
        }
        #pragma unroll
        for (int kk = 0; kk < 16; kk++) {
            float4 a0 = *(const float4*)&HSH(cur, kk, rm);
            float4 a1 = *(const float4*)&HSH(cur, kk, rm + 64);
            float4 b0 = *(const float4*)&WSH(cur, kk, cn);
            float4 b1 = *(const float4*)&WSH(cur, kk, cn + 64);
            float a[8] = {a0.x, a0.y, a0.z, a0.w, a1.x, a1.y, a1.z, a1.w};
            float b[8] = {b0.x, b0.y, b0.z, b0.w, b1.x, b1.y, b1.z, b1.w};
            #pragma unroll
            for (int i = 0; i < 8; i++)
                #pragma unroll
                for (int j = 0; j < 8; j++)
                    acc[i][j] += a[i] * b[j];
        }
        if (kbi < 15) {
            #pragma unroll
            for (int i = 0; i < 2; i++) {
                int idx = tid * 2 + i;
                int kk = idx >> 5, c = (idx & 31) * 4;
                *(float4*)&WSH(cur ^ 1, kk, c) = pw[i];
                int r = idx >> 2, kc = (idx & 3) * 4;
                HSH(cur ^ 1, kc + 0, r) = ph[i].x;
                HSH(cur ^ 1, kc + 1, r) = ph[i].y;
                HSH(cur ^ 1, kc + 2, r) = ph[i].z;
                HSH(cur ^ 1, kc + 3, r) = ph[i].w;
            }
        }
        __syncthreads();
        cur ^= 1;
    }

    // epilogue
    float4 bia0 = *(const float4*)&bb[cn];
    float4 bia1 = *(const float4*)&bb[cn + 64];
    float bias[8] = {bia0.x, bia0.y, bia0.z, bia0.w, bia1.x, bia1.y, bia1.z, bia1.w};
    float psum[8], psq[8];
    #pragma unroll
    for (int j = 0; j < 8; j++) { psum[j] = 0.f; psq[j] = 0.f; }
    #pragma unroll
    for (int i = 0; i < 8; i++) {
        int row = row0 + ((i < 4) ? (rm + i) : (64 + rm + i - 4));
        if (row < nt) {
            float v[8];
            #pragma unroll
            for (int j = 0; j < 8; j++) {
                v[j] = acc[i][j] + bias[j];
                psum[j] += v[j];
                psq[j]  += v[j] * v[j];
            }
            *(float4*)(g_bufB + (size_t)row * H_ + cn)      = make_float4(v[0], v[1], v[2], v[3]);
            *(float4*)(g_bufB + (size_t)row * H_ + cn + 64) = make_float4(v[4], v[5], v[6], v[7]);
        }
    }
    __syncthreads();
    float* sumS = meanS;
    float* sqS  = meanS + 2048;
    #pragma unroll
    for (int j = 0; j < 4; j++) {
        sumS[ty * 128 + cn + j]      = psum[j];
        sumS[ty * 128 + cn + 64 + j] = psum[4 + j];
        sqS [ty * 128 + cn + j]      = psq[j];
        sqS [ty * 128 + cn + 64 + j] = psq[4 + j];
    }
    __syncthreads();
    if (tid < 128) {
        float s = 0.f, q = 0.f;
        #pragma unroll
        for (int t = 0; t < 16; t++) {
            s += sumS[t * 128 + tid];
            q += sqS [t * 128 + tid];
        }
        atomicAdd(&g_colsum[slot * H_ + tid], s);
        atomicAdd(&g_colsq [slot * H_ + tid], q);
    }
    #undef WSH
    #undef HSH
}

// ---------------- mega: BN+score -> topk -> gather+readout -> remap+CSR (or MLP head) ----------------
__global__ __launch_bounds__(1024)
void mega_kernel(const int* __restrict__ ei, int b, int ncur, int k,
                 const float* __restrict__ gw, const float* __restrict__ be,
                 const float* __restrict__ p, float invnt,
                 const float* __restrict__ Wd1, const float* __restrict__ bd1,
                 const float* __restrict__ Wd2, const float* __restrict__ bd2,
                 float* __restrict__ out) {
    extern __shared__ char smx[];
    float* s_score = (float*)(smx);
    int*   s_id    = (int*)(smx + 4096);
    int*   s_map   = (int*)(smx + 8192);
    int*   s_cnt   = (int*)(smx + 12288);
    int*   s_cur   = (int*)(smx + 16384);
    float* s_red   = (float*)(smx + 20480);   // [32][128] sum, then [32][128] max

    int g = blockIdx.x, tid = threadIdx.x;
    int lane = tid & 31, wid = tid >> 5;
    int c = lane * 4;

    // ---- phase 1: BN + relu + score ----
    float4 cs = *(const float4*)&g_colsum[b * H_ + c];
    float4 cq = *(const float4*)&g_colsq [b * H_ + c];
    float4 gv = *(const float4*)&gw[c];
    float4 bv = *(const float4*)&be[c];
    float4 pv = *(const float4*)&p[c];
    float mu[4], rs[4];
    {
        float css[4] = {cs.x, cs.y, cs.z, cs.w};
        float cqq[4] = {cq.x, cq.y, cq.z, cq.w};
        #pragma unroll
        for (int j = 0; j < 4; j++) {
            mu[j] = css[j] * invnt;
            float var = cqq[j] * invnt - mu[j] * mu[j];
            rs[j] = rsqrtf(var + 1e-5f);
        }
    }
    float pn = pv.x * pv.x + pv.y * pv.y + pv.z * pv.z + pv.w * pv.w;
    #pragma unroll
    for (int o = 16; o > 0; o >>= 1) pn += __shfl_xor_sync(0xffffffffu, pn, o);
    float ipn = rsqrtf(pn);

    for (int r = wid; r < ncur; r += 32) {
        float* hr = g_bufB + (size_t)(g * ncur + r) * H_ + c;
        float4 h = *(const float4*)hr;
        float v0 = fmaxf((h.x - mu[0]) * rs[0] * gv.x + bv.x, 0.f);
        float v1 = fmaxf((h.y - mu[1]) * rs[1] * gv.y + bv.y, 0.f);
        float v2 = fmaxf((h.z - mu[2]) * rs[2] * gv.z + bv.z, 0.f);
        float v3 = fmaxf((h.w - mu[3]) * rs[3] * gv.w + bv.w, 0.f);
        *(float4*)hr = make_float4(v0, v1, v2, v3);
        float dot = v0 * pv.x + v1 * pv.y + v2 * pv.z + v3 * pv.w;
        #pragma unroll
        for (int o = 16; o > 0; o >>= 1) dot += __shfl_down_sync(0xffffffffu, dot, o);
        if (lane == 0) s_score[r] = dot * ipn;
    }
    if (tid >= ncur) s_score[tid] = -FLT_MAX;
    s_id[tid] = (tid < ncur) ? tid : (1024 + tid);
    __syncthreads();

    // ---- phase 2: bitonic sort desc (tie: smaller id first) ----
    for (int kk = 2; kk <= 1024; kk <<= 1) {
        for (int j = kk >> 1; j > 0; j >>= 1) {
            int i = tid;
            int ixj = i ^ j;
            if (ixj > i) {
                float si = s_score[i], sj = s_score[ixj];
                int ii = s_id[i], ij = s_id[ixj];
                bool less = (si < sj) || (si == sj && ii > ij);
                bool up = ((i & kk) == 0);
                if (less == up) {
                    s_score[i] = sj; s_score[ixj] = si;
                    s_id[i] = ij;    s_id[ixj] = ii;
                }
            }
            __syncthreads();
        }
    }

    // ---- phase 3: map (only needed when remapping) ----
    if (b < 3) {
        s_map[tid] = -1;
        __syncthreads();
        if (tid < k) s_map[s_id[tid]] = tid;
    }

    // ---- phase 4: gather + tanh gate + readout ----
    float4 rsum = make_float4(0.f, 0.f, 0.f, 0.f);
    float4 rmax = make_float4(-FLT_MAX, -FLT_MAX, -FLT_MAX, -FLT_MAX);
    for (int nw = wid; nw < k; nw += 32) {
        int old = s_id[nw];
        float t = tanhf(s_score[nw]);
        float4 h = *(const float4*)(g_bufB + (size_t)(g * ncur + old) * H_ + c);
        h.x *= t; h.y *= t; h.z *= t; h.w *= t;
        *(float4*)(g_bufA + (size_t)(g * k + nw) * H_ + c) = h;
        rsum.x += h.x; rsum.y += h.y; rsum.z += h.z; rsum.w += h.w;
        rmax.x = fmaxf(rmax.x, h.x); rmax.y = fmaxf(rmax.y, h.y);
        rmax.z = fmaxf(rmax.z, h.z); rmax.w = fmaxf(rmax.w, h.w);
    }
    *(float4*)&s_red[wid * 128 + c]        = rsum;
    *(float4*)&s_red[4096 + wid * 128 + c] = rmax;
    __syncthreads();
    if (tid < 128) {
        float s = 0.f, m = -FLT_MAX;
        #pragma unroll
        for (int w = 0; w < 32; w++) {
            s += s_red[w * 128 + tid];
            m = fmaxf(m, s_red[4096 + w * 128 + tid]);
        }
        g_flat[g * 1024 + b * 256 + tid]       = s;
        g_flat[g * 1024 + b * 256 + 128 + tid] = m;
    }
    __syncthreads();

    if (b < 3) {
        // ---- phase 5: remap + count + scan + fill for next block ----
        for (int i = tid; i < k; i += 1024) s_cnt[i] = 0;
        __syncthreads();
        const int eb = g * EPG;
        for (int e = tid; e < EPG; e += 1024) {
            int s, d;
            if (b == 0) { s = ei[eb + e] - (g << 10); d = ei[EDGES + eb + e] - (g << 10); }
            else        { s = g_srcL[eb + e]; d = g_dstL[eb + e]; }
            int ns = -1, nd = -1;
            if (s >= 0) {
                ns = s_map[s];
                nd = s_map[d];
                if (ns < 0 || nd < 0) { ns = -1; nd = -1; }
                else atomicAdd(&s_cnt[nd], 1);
            }
            g_srcL[eb + e] = ns;
            g_dstL[eb + e] = nd;
        }
        __syncthreads();
        // block scan of s_cnt[0..k)
        int v = (tid < k) ? s_cnt[tid] : 0;
        int inc = v;
        #pragma unroll
        for (int o = 1; o < 32; o <<= 1) {
            int t = __shfl_up_sync(0xffffffffu, inc, o);
            if (lane >= o) inc += t;
        }
        int* wsum = (int*)s_red;
        if (lane == 31) wsum[wid] = inc;
        __syncthreads();
        if (wid == 0) {
            int ws = wsum[lane], wi = ws;
            #pragma unroll
            for (int o = 1; o < 32; o <<= 1) {
                int t = __shfl_up_sync(0xffffffffu, wi, o);
                if (lane >= o) wi += t;
            }
            wsum[lane] = wi - ws;
        }
        __syncthreads();
        int ex = wsum[wid] + inc - v;
        if (tid < k) {
            s_cur[tid] = ex;                  // exclusive offset (local)
            g_off [g * k + tid] = eb + ex;
            g_cnti[g * k + tid] = v;
            s_id[tid] = 0;                    // reuse as fill cursor
        }
        __syncthreads();
        for (int e = tid; e < EPG; e += 1024) {
            int ns = g_srcL[eb + e];
            if (ns >= 0) {
                int nd = g_dstL[eb + e];
                int pos = atomicAdd(&s_id[nd], 1);
                g_csr[eb + s_cur[nd] + pos] = g * k + ns;
            }
        }
    } else {
        // ---- MLP head per graph ----
        float* a = (float*)s_map;      // 1024 floats
        a[tid] = g_flat[g * 1024 + tid];
        __syncthreads();
        float* hd = (float*)s_cnt;     // 512 floats
        if (tid < 512) {
            float a0 = 0.f, a1 = 0.f, a2 = 0.f, a3 = 0.f;
            #pragma unroll 4
            for (int kk = 0; kk < 1024; kk += 4) {
                a0 += a[kk + 0] * Wd1[(kk + 0) * 512 + tid];
                a1 += a[kk + 1] * Wd1[(kk + 1) * 512 + tid];
                a2 += a[kk + 2] * Wd1[(kk + 2) * 512 + tid];
                a3 += a[kk + 3] * Wd1[(kk + 3) * 512 + tid];
            }
            hd[tid] = fmaxf(a0 + a1 + a2 + a3 + bd1[tid], 0.f);
        }
        __syncthreads();
        if (tid < 320) {
            int cc = tid >> 5, l = tid & 31;
            float acc = 0.f;
            for (int kk = l; kk < 512; kk += 32) acc += hd[kk] * Wd2[kk * 10 + cc];
            #pragma unroll
            for (int o = 16; o > 0; o >>= 1) acc += __shfl_down_sync(0xffffffffu, acc, o);
            if (l == 0) out[g * 10 + cc] = acc + bd2[cc];
        }
    }
}

// ---------------- launcher ----------------
extern "C" void kernel_launch(void* const* d_in, const int* in_sizes, int n_in,
                              void* d_out, int out_size) {
    const float* x  = (const float*)d_in[0];
    const int*   ei = (const int*)d_in[1];
    const float *Wl[4], *Wr[4], *bb[4], *gw[4], *be[4], *pp[4];
    int idx = 3;
    for (int b = 0; b < 4; b++) {
        Wl[b] = (const float*)d_in[idx++];
        Wr[b] = (const float*)d_in[idx++];
        bb[b] = (const float*)d_in[idx++];
        gw[b] = (const float*)d_in[idx++];
        be[b] = (const float*)d_in[idx++];
        pp[b] = (const float*)d_in[idx++];
    }
    const float* Wd1 = (const float*)d_in[27];
    const float* bd1 = (const float*)d_in[28];
    const float* Wd2 = (const float*)d_in[29];
    const float* bd2 = (const float*)d_in[30];
    float* out = (float*)d_out;

    cudaFuncSetAttribute(gemm_kernel, cudaFuncAttributeMaxDynamicSharedMemorySize,
                         SMEM_GEMM_BYTES);
    cudaFuncSetAttribute(mega_kernel, cudaFuncAttributeMaxDynamicSharedMemorySize,
                         MEGA_SMEM);

    csr0_kernel<<<G_, 1024>>>(ei);

    for (int b = 0; b < 4; b++) {
        int ncur = NCUR_H[b];
        int k    = KSEL_H[b];
        int nt   = G_ * ncur;
        int first = (b == 0) ? 1 : 0;

        gemm_kernel<<<(nt + 127) / 128, 256, SMEM_GEMM_BYTES>>>(
            x, first, b, Wl[b], Wr[b], bb[b], nt);
        mega_kernel<<<G_, 1024, MEGA_SMEM>>>(
            ei, b, ncur, k, gw[b], be[b], pp[b], 1.0f / (float)nt,
            Wd1, bd1, Wd2, bd2, out);
    }
}

// round 7
// speedup vs baseline: 2.1721x; 1.1258x over previous
#include <cuda_runtime.h>
#include <math.h>
#include <float.h>

// ---------------- problem constants ----------------
#define G_      32
#define EPG     16384                 // edges per graph
#define EDGES   (G_ * EPG)
#define H_      128
#define NT_MAX  32768

static const int NCUR_H[4] = {1024, 820, 656, 525};
static const int KSEL_H[4] = {820, 656, 525, 420};

// gemm smem: meanS 64x132 + W 2x16x128 + H 2x16x64  (floats)
#define SMEM_GEMM_BYTES ((64 * 132 + 2 * 16 * 128 + 2 * 16 * 64) * 4)
// mega smem: 5 x 4KB arrays + 32KB readout reduce
#define MEGA_SMEM (5 * 4096 + 32 * 128 * 2 * 4)

// ---------------- device scratch ----------------
__device__ __align__(16) float g_bufA[NT_MAX * H_];  // pooled h (input of next block)
__device__ __align__(16) float g_bufB[NT_MAX * H_];  // conv out -> BN'd h
__device__ int   g_cnti[NT_MAX];
__device__ int   g_off [NT_MAX];       // absolute csr base per node
__device__ int   g_csr [EDGES];        // neighbor global row ids grouped by dst
__device__ int   g_srcL[EDGES];
__device__ int   g_dstL[EDGES];
__device__ float g_score[NT_MAX];
__device__ __align__(16) float g_colsum[4 * H_];
__device__ __align__(16) float g_colsq [4 * H_];
__device__ float g_flat[G_ * 1024];

// ---------------- csr0: per-graph count+scan+fill for input edges ----------------
__global__ __launch_bounds__(1024)
void csr0_kernel(const int* __restrict__ ei) {
    __shared__ int cnt[1024], off[1024], cur[1024];
    __shared__ int wsum[32];
    int g = blockIdx.x, tid = threadIdx.x;
    int lane = tid & 31, wid = tid >> 5;
    cnt[tid] = 0;
    __syncthreads();
    const int* srcp = ei + g * EPG;
    const int* dstp = ei + EDGES + g * EPG;
    for (int e = tid; e < EPG; e += 1024)
        atomicAdd(&cnt[dstp[e] - (g << 10)], 1);
    __syncthreads();
    int v = cnt[tid];
    int inc = v;
    #pragma unroll
    for (int o = 1; o < 32; o <<= 1) {
        int t = __shfl_up_sync(0xffffffffu, inc, o);
        if (lane >= o) inc += t;
    }
    if (lane == 31) wsum[wid] = inc;
    __syncthreads();
    if (wid == 0) {
        int ws = wsum[lane], wi = ws;
        #pragma unroll
        for (int o = 1; o < 32; o <<= 1) {
            int t = __shfl_up_sync(0xffffffffu, wi, o);
            if (lane >= o) wi += t;
        }
        wsum[lane] = wi - ws;
    }
    __syncthreads();
    int ex = wsum[wid] + inc - v;
    off[tid] = ex;
    g_off [g * 1024 + tid] = g * EPG + ex;
    g_cnti[g * 1024 + tid] = v;
    cur[tid] = 0;
    __syncthreads();
    for (int e = tid; e < EPG; e += 1024) {
        int s = srcp[e];
        int d = dstp[e] - (g << 10);
        int pos = atomicAdd(&cur[d], 1);
        g_csr[g * EPG + off[d] + pos] = s;
    }
    if (g == 0 && tid < 4 * H_) { g_colsum[tid] = 0.f; g_colsq[tid] = 0.f; }
}

// ---------------- fused gather-mean + GEMM + BN-stats (64-row tile) ----------------
__global__ __launch_bounds__(256, 3)
void gemm_kernel(const float* __restrict__ x, int first, int slot,
                 const float* __restrict__ Wl, const float* __restrict__ Wr,
                 const float* __restrict__ bb, int nt) {
    extern __shared__ float smem[];
    float* meanS = smem;                        // [64][132]
    float* WshB  = smem + 64 * 132;             // [2][16][128]
    float* HshB  = WshB + 2 * 16 * 128;         // [2][16][64]
    #define WSH(b,k,c) WshB[(b) * 2048 + (k) * 128 + (c)]
    #define HSH(b,k,m) HshB[(b) * 1024 + (k) * 64 + (m)]

    const float* hin = first ? x : g_bufA;
    int row0 = blockIdx.x * 64;
    int tid = threadIdx.x;
    int w = tid >> 5, lane = tid & 31;
    int tx = tid & 15, ty = tid >> 4;
    int rm = ty * 4, cn = tx * 4;

    // prefetch W block 0 behind the gather
    float4 pw[2];
    #pragma unroll
    for (int i = 0; i < 2; i++) {
        int idx = tid * 2 + i;
        int kk = idx >> 5, c = (idx & 31) * 4;
        pw[i] = *(const float4*)(Wl + (size_t)kk * H_ + c);
    }

    // ---- phase 1: gather means (8 rows per warp, 8 loads in flight) ----
    for (int i = 0; i < 8; i++) {
        int rl = w * 8 + i;
        int row = row0 + rl;
        float4 acc = make_float4(0.f, 0.f, 0.f, 0.f);
        if (row < nt) {
            int deg  = g_cnti[row];
            int base = g_off[row];
            int j = 0;
            for (; j + 8 <= deg; j += 8) {
                int s0 = g_csr[base + j + 0];
                int s1 = g_csr[base + j + 1];
                int s2 = g_csr[base + j + 2];
                int s3 = g_csr[base + j + 3];
                int s4 = g_csr[base + j + 4];
                int s5 = g_csr[base + j + 5];
                int s6 = g_csr[base + j + 6];
                int s7 = g_csr[base + j + 7];
                float4 v0 = *((const float4*)(hin + (size_t)s0 * H_) + lane);
                float4 v1 = *((const float4*)(hin + (size_t)s1 * H_) + lane);
                float4 v2 = *((const float4*)(hin + (size_t)s2 * H_) + lane);
                float4 v3 = *((const float4*)(hin + (size_t)s3 * H_) + lane);
                float4 v4 = *((const float4*)(hin + (size_t)s4 * H_) + lane);
                float4 v5 = *((const float4*)(hin + (size_t)s5 * H_) + lane);
                float4 v6 = *((const float4*)(hin + (size_t)s6 * H_) + lane);
                float4 v7 = *((const float4*)(hin + (size_t)s7 * H_) + lane);
                acc.x += ((v0.x + v1.x) + (v2.x + v3.x)) + ((v4.x + v5.x) + (v6.x + v7.x));
                acc.y += ((v0.y + v1.y) + (v2.y + v3.y)) + ((v4.y + v5.y) + (v6.y + v7.y));
                acc.z += ((v0.z + v1.z) + (v2.z + v3.z)) + ((v4.z + v5.z) + (v6.z + v7.z));
                acc.w += ((v0.w + v1.w) + (v2.w + v3.w)) + ((v4.w + v5.w) + (v6.w + v7.w));
            }
            for (; j < deg; j++) {
                int s0 = g_csr[base + j];
                float4 a = *((const float4*)(hin + (size_t)s0 * H_) + lane);
                acc.x += a.x; acc.y += a.y; acc.z += a.z; acc.w += a.w;
            }
            float inv = 1.0f / fmaxf((float)deg, 1.0f);
            acc.x *= inv; acc.y *= inv; acc.z *= inv; acc.w *= inv;
        }
        *(float4*)&meanS[rl * 132 + lane * 4] = acc;
    }
    #pragma unroll
    for (int i = 0; i < 2; i++) {
        int idx = tid * 2 + i;
        int kk = idx >> 5, c = (idx & 31) * 4;
        *(float4*)&WSH(0, kk, c) = pw[i];
    }
    __syncthreads();

    float acc[4][8];
    #pragma unroll
    for (int i = 0; i < 4; i++)
        #pragma unroll
        for (int j = 0; j < 8; j++) acc[i][j] = 0.f;

    int cur = 0;
    float4 ph;  // single H-tile float4 per thread

    // ---- first half: k = 0..127, A from meanS ----
    for (int kbi = 0; kbi < 8; kbi++) {
        int kwb = (kbi + 1) * 16;
        #pragma unroll
        for (int i = 0; i < 2; i++) {
            int idx = tid * 2 + i;
            int kk = idx >> 5, c = (idx & 31) * 4;
            int kw = kwb + kk;
            const float* ws = (kw < 128) ? (Wl + (size_t)kw * H_ + c)
                                         : (Wr + (size_t)(kw - 128) * H_ + c);
            pw[i] = *(const float4*)ws;
        }
        if (kbi == 7) {
            int r = tid >> 2, kc = (tid & 3) * 4;
            int row = row0 + r;
            ph = (row < nt) ? *(const float4*)(hin + (size_t)row * H_ + kc)
                            : make_float4(0.f, 0.f, 0.f, 0.f);
        }
        int kb = kbi * 16;
        #pragma unroll
        for (int kk = 0; kk < 16; kk++) {
            int kcol = kb + kk;
            float a[4];
            #pragma unroll
            for (int i = 0; i < 4; i++) a[i] = meanS[(rm + i) * 132 + kcol];
            float4 b0 = *(const float4*)&WSH(cur, kk, cn);
            float4 b1 = *(const float4*)&WSH(cur, kk, cn + 64);
            float b[8] = {b0.x, b0.y, b0.z, b0.w, b1.x, b1.y, b1.z, b1.w};
            #pragma unroll
            for (int i = 0; i < 4; i++)
                #pragma unroll
                for (int j = 0; j < 8; j++)
                    acc[i][j] += a[i] * b[j];
        }
        #pragma unroll
        for (int i = 0; i < 2; i++) {
            int idx = tid * 2 + i;
            int kk = idx >> 5, c = (idx & 31) * 4;
            *(float4*)&WSH(cur ^ 1, kk, c) = pw[i];
        }
        if (kbi == 7) {
            int r = tid >> 2, kc = (tid & 3) * 4;
            HSH(cur ^ 1, kc + 0, r) = ph.x;
            HSH(cur ^ 1, kc + 1, r) = ph.y;
            HSH(cur ^ 1, kc + 2, r) = ph.z;
            HSH(cur ^ 1, kc + 3, r) = ph.w;
        }
        __syncthreads();
        cur ^= 1;
    }

    // ---- second half: k = 128..255, A from Hsh ----
    for (int kbi = 8; kbi < 16; kbi++) {
        if (kbi < 15) {
            int kwb = (kbi + 1) * 16;
            int hb  = (kbi + 1 - 8) * 16;
            #pragma unroll
            for (int i = 0; i < 2; i++) {
                int idx = tid * 2 + i;
                int kk = idx >> 5, c = (idx & 31) * 4;
                pw[i] = *(const float4*)(Wr + (size_t)(kwb + kk - 128) * H_ + c);
            }
            int r = tid >> 2, kc = (tid & 3) * 4;
            int row = row0 + r;
            ph = (row < nt) ? *(const float4*)(hin + (size_t)row * H_ + hb + kc)
                            : make_float4(0.f, 0.f, 0.f, 0.f);
        }
        #pragma unroll
        for (int kk = 0; kk < 16; kk++) {
            float4 a0 = *(const float4*)&HSH(cur, kk, rm);
            float4 b0 = *(const float4*)&WSH(cur, kk, cn);
            float4 b1 = *(const float4*)&WSH(cur, kk, cn + 64);
            float a[4] = {a0.x, a0.y, a0.z, a0.w};
            float b[8] = {b0.x, b0.y, b0.z, b0.w, b1.x, b1.y, b1.z, b1.w};
            #pragma unroll
            for (int i = 0; i < 4; i++)
                #pragma unroll
                for (int j = 0; j < 8; j++)
                    acc[i][j] += a[i] * b[j];
        }
        if (kbi < 15) {
            #pragma unroll
            for (int i = 0; i < 2; i++) {
                int idx = tid * 2 + i;
                int kk = idx >> 5, c = (idx & 31) * 4;
                *(float4*)&WSH(cur ^ 1, kk, c) = pw[i];
            }
            int r = tid >> 2, kc = (tid & 3) * 4;
            HSH(cur ^ 1, kc + 0, r) = ph.x;
            HSH(cur ^ 1, kc + 1, r) = ph.y;
            HSH(cur ^ 1, kc + 2, r) = ph.z;
            HSH(cur ^ 1, kc + 3, r) = ph.w;
        }
        __syncthreads();
        cur ^= 1;
    }

    // ---- epilogue ----
    float4 bia0 = *(const float4*)&bb[cn];
    float4 bia1 = *(const float4*)&bb[cn + 64];
    float bias[8] = {bia0.x, bia0.y, bia0.z, bia0.w, bia1.x, bia1.y, bia1.z, bia1.w};
    float psum[8], psq[8];
    #pragma unroll
    for (int j = 0; j < 8; j++) { psum[j] = 0.f; psq[j] = 0.f; }
    #pragma unroll
    for (int i = 0; i < 4; i++) {
        int row = row0 + rm + i;
        if (row < nt) {
            float v[8];
            #pragma unroll
            for (int j = 0; j < 8; j++) {
                v[j] = acc[i][j] + bias[j];
                psum[j] += v[j];
                psq[j]  += v[j] * v[j];
            }
            *(float4*)(g_bufB + (size_t)row * H_ + cn)      = make_float4(v[0], v[1], v[2], v[3]);
            *(float4*)(g_bufB + (size_t)row * H_ + cn + 64) = make_float4(v[4], v[5], v[6], v[7]);
        }
    }
    __syncthreads();
    float* sumS = meanS;          // [16][128]
    float* sqS  = meanS + 2048;   // [16][128]
    #pragma unroll
    for (int j = 0; j < 4; j++) {
        sumS[ty * 128 + cn + j]      = psum[j];
        sumS[ty * 128 + cn + 64 + j] = psum[4 + j];
        sqS [ty * 128 + cn + j]      = psq[j];
        sqS [ty * 128 + cn + 64 + j] = psq[4 + j];
    }
    __syncthreads();
    if (tid < 128) {
        float s = 0.f, q = 0.f;
        #pragma unroll
        for (int t = 0; t < 16; t++) {
            s += sumS[t * 128 + tid];
            q += sqS [t * 128 + tid];
        }
        atomicAdd(&g_colsum[slot * H_ + tid], s);
        atomicAdd(&g_colsq [slot * H_ + tid], q);
    }
    #undef WSH
    #undef HSH
}

// ---------------- wide BN + ReLU + score ----------------
__global__ __launch_bounds__(256)
void bnscore_kernel(const float* __restrict__ gw, const float* __restrict__ be,
                    const float* __restrict__ p, int nt, float invnt, int slot) {
    int row = blockIdx.x * 8 + (threadIdx.x >> 5);
    int lane = threadIdx.x & 31;
    if (row >= nt) return;
    int c = lane * 4;
    float4 h  = *(const float4*)(g_bufB + (size_t)row * H_ + c);
    float4 cs = *(const float4*)&g_colsum[slot * H_ + c];
    float4 cq = *(const float4*)&g_colsq [slot * H_ + c];
    float4 gv = *(const float4*)&gw[c];
    float4 bv = *(const float4*)&be[c];
    float4 pv = *(const float4*)&p[c];
    float hh[4]  = {h.x, h.y, h.z, h.w};
    float css[4] = {cs.x, cs.y, cs.z, cs.w};
    float cqq[4] = {cq.x, cq.y, cq.z, cq.w};
    float gg[4]  = {gv.x, gv.y, gv.z, gv.w};
    float bbv[4] = {bv.x, bv.y, bv.z, bv.w};
    float pp[4]  = {pv.x, pv.y, pv.z, pv.w};
    float out[4];
    float dot = 0.f, pn = 0.f;
    #pragma unroll
    for (int j = 0; j < 4; j++) {
        float mu = css[j] * invnt;
        float var = cqq[j] * invnt - mu * mu;
        float r = rsqrtf(var + 1e-5f);
        float v = (hh[j] - mu) * r * gg[j] + bbv[j];
        v = fmaxf(v, 0.f);
        out[j] = v;
        dot += v * pp[j];
        pn  += pp[j] * pp[j];
    }
    *(float4*)(g_bufB + (size_t)row * H_ + c) = make_float4(out[0], out[1], out[2], out[3]);
    #pragma unroll
    for (int o = 16; o > 0; o >>= 1) {
        dot += __shfl_down_sync(0xffffffffu, dot, o);
        pn  += __shfl_down_sync(0xffffffffu, pn, o);
    }
    if (lane == 0) g_score[row] = dot * rsqrtf(pn);
}

// ---------------- mega: topk -> gather+readout -> remap+CSR (or MLP head) ----------------
__global__ __launch_bounds__(1024)
void mega_kernel(const int* __restrict__ ei, int b, int ncur, int k,
                 const float* __restrict__ Wd1, const float* __restrict__ bd1,
                 const float* __restrict__ Wd2, const float* __restrict__ bd2,
                 float* __restrict__ out) {
    extern __shared__ char smx[];
    float* s_score = (float*)(smx);
    int*   s_id    = (int*)(smx + 4096);
    int*   s_map   = (int*)(smx + 8192);
    int*   s_cnt   = (int*)(smx + 12288);
    int*   s_cur   = (int*)(smx + 16384);
    float* s_red   = (float*)(smx + 20480);   // [32][128] sum, [32][128] max

    int g = blockIdx.x, tid = threadIdx.x;
    int lane = tid & 31, wid = tid >> 5;
    int c = lane * 4;

    s_score[tid] = (tid < ncur) ? g_score[g * ncur + tid] : -FLT_MAX;
    s_id[tid] = (tid < ncur) ? tid : (1024 + tid);
    __syncthreads();

    // bitonic sort desc (tie: smaller id first)
    for (int kk = 2; kk <= 1024; kk <<= 1) {
        for (int j = kk >> 1; j > 0; j >>= 1) {
            int i = tid;
            int ixj = i ^ j;
            if (ixj > i) {
                float si = s_score[i], sj = s_score[ixj];
                int ii = s_id[i], ij = s_id[ixj];
                bool less = (si < sj) || (si == sj && ii > ij);
                bool up = ((i & kk) == 0);
                if (less == up) {
                    s_score[i] = sj; s_score[ixj] = si;
                    s_id[i] = ij;    s_id[ixj] = ii;
                }
            }
            __syncthreads();
        }
    }

    if (b < 3) {
        s_map[tid] = -1;
        __syncthreads();
        if (tid < k) s_map[s_id[tid]] = tid;
    }

    // gather + tanh gate + readout
    float4 rsum = make_float4(0.f, 0.f, 0.f, 0.f);
    float4 rmax = make_float4(-FLT_MAX, -FLT_MAX, -FLT_MAX, -FLT_MAX);
    for (int nw = wid; nw < k; nw += 32) {
        int old = s_id[nw];
        float t = tanhf(s_score[nw]);
        float4 h = *(const float4*)(g_bufB + (size_t)(g * ncur + old) * H_ + c);
        h.x *= t; h.y *= t; h.z *= t; h.w *= t;
        *(float4*)(g_bufA + (size_t)(g * k + nw) * H_ + c) = h;
        rsum.x += h.x; rsum.y += h.y; rsum.z += h.z; rsum.w += h.w;
        rmax.x = fmaxf(rmax.x, h.x); rmax.y = fmaxf(rmax.y, h.y);
        rmax.z = fmaxf(rmax.z, h.z); rmax.w = fmaxf(rmax.w, h.w);
    }
    *(float4*)&s_red[wid * 128 + c]        = rsum;
    *(float4*)&s_red[4096 + wid * 128 + c] = rmax;
    __syncthreads();
    if (tid < 128) {
        float s = 0.f, m = -FLT_MAX;
        #pragma unroll
        for (int w = 0; w < 32; w++) {
            s += s_red[w * 128 + tid];
            m = fmaxf(m, s_red[4096 + w * 128 + tid]);
        }
        g_flat[g * 1024 + b * 256 + tid]       = s;
        g_flat[g * 1024 + b * 256 + 128 + tid] = m;
    }
    __syncthreads();

    if (b < 3) {
        // remap + count + scan + fill next-block CSR
        for (int i = tid; i < k; i += 1024) s_cnt[i] = 0;
        __syncthreads();
        const int eb = g * EPG;
        for (int e = tid; e < EPG; e += 1024) {
            int s, d;
            if (b == 0) { s = ei[eb + e] - (g << 10); d = ei[EDGES + eb + e] - (g << 10); }
            else        { s = g_srcL[eb + e]; d = g_dstL[eb + e]; }
            int ns = -1, nd = -1;
            if (s >= 0) {
                ns = s_map[s];
                nd = s_map[d];
                if (ns < 0 || nd < 0) { ns = -1; nd = -1; }
                else atomicAdd(&s_cnt[nd], 1);
            }
            g_srcL[eb + e] = ns;
            g_dstL[eb + e] = nd;
        }
        __syncthreads();
        int v = (tid < k) ? s_cnt[tid] : 0;
        int inc = v;
        #pragma unroll
        for (int o = 1; o < 32; o <<= 1) {
            int t = __shfl_up_sync(0xffffffffu, inc, o);
            if (lane >= o) inc += t;
        }
        int* wsum = (int*)s_red;
        if (lane == 31) wsum[wid] = inc;
        __syncthreads();
        if (wid == 0) {
            int ws = wsum[lane], wi = ws;
            #pragma unroll
            for (int o = 1; o < 32; o <<= 1) {
                int t = __shfl_up_sync(0xffffffffu, wi, o);
                if (lane >= o) wi += t;
            }
            wsum[lane] = wi - ws;
        }
        __syncthreads();
        int ex = wsum[wid] + inc - v;
        if (tid < k) {
            s_cur[tid] = ex;
            g_off [g * k + tid] = eb + ex;
            g_cnti[g * k + tid] = v;
            s_id[tid] = 0;
        }
        __syncthreads();
        for (int e = tid; e < EPG; e += 1024) {
            int ns = g_srcL[eb + e];
            if (ns >= 0) {
                int nd = g_dstL[eb + e];
                int pos = atomicAdd(&s_id[nd], 1);
                g_csr[eb + s_cur[nd] + pos] = g * k + ns;
            }
        }
    } else {
        // MLP head per graph
        float* a = (float*)s_map;
        a[tid] = g_flat[g * 1024 + tid];
        __syncthreads();
        float* hd = (float*)s_cnt;
        if (tid < 512) {
            float a0 = 0.f, a1 = 0.f, a2 = 0.f, a3 = 0.f;
            #pragma unroll 4
            for (int kk = 0; kk < 1024; kk += 4) {
                a0 += a[kk + 0] * Wd1[(kk + 0) * 512 + tid];
                a1 += a[kk + 1] * Wd1[(kk + 1) * 512 + tid];
                a2 += a[kk + 2] * Wd1[(kk + 2) * 512 + tid];
                a3 += a[kk + 3] * Wd1[(kk + 3) * 512 + tid];
            }
            hd[tid] = fmaxf(a0 + a1 + a2 + a3 + bd1[tid], 0.f);
        }
        __syncthreads();
        if (tid < 320) {
            int cc = tid >> 5, l = tid & 31;
            float acc = 0.f;
            for (int kk = l; kk < 512; kk += 32) acc += hd[kk] * Wd2[kk * 10 + cc];
            #pragma unroll
            for (int o = 16; o > 0; o >>= 1) acc += __shfl_down_sync(0xffffffffu, acc, o);
            if (l == 0) out[g * 10 + cc] = acc + bd2[cc];
        }
    }
}

// ---------------- launcher ----------------
extern "C" void kernel_launch(void* const* d_in, const int* in_sizes, int n_in,
                              void* d_out, int out_size) {
    const float* x  = (const float*)d_in[0];
    const int*   ei = (const int*)d_in[1];
    const float *Wl[4], *Wr[4], *bb[4], *gw[4], *be[4], *pp[4];
    int idx = 3;
    for (int b = 0; b < 4; b++) {
        Wl[b] = (const float*)d_in[idx++];
        Wr[b] = (const float*)d_in[idx++];
        bb[b] = (const float*)d_in[idx++];
        gw[b] = (const float*)d_in[idx++];
        be[b] = (const float*)d_in[idx++];
        pp[b] = (const float*)d_in[idx++];
    }
    const float* Wd1 = (const float*)d_in[27];
    const float* bd1 = (const float*)d_in[28];
    const float* Wd2 = (const float*)d_in[29];
    const float* bd2 = (const float*)d_in[30];
    float* out = (float*)d_out;

    cudaFuncSetAttribute(gemm_kernel, cudaFuncAttributeMaxDynamicSharedMemorySize,
                         SMEM_GEMM_BYTES);
    cudaFuncSetAttribute(mega_kernel, cudaFuncAttributeMaxDynamicSharedMemorySize,
                         MEGA_SMEM);

    csr0_kernel<<<G_, 1024>>>(ei);

    for (int b = 0; b < 4; b++) {
        int ncur = NCUR_H[b];
        int k    = KSEL_H[b];
        int nt   = G_ * ncur;
        int first = (b == 0) ? 1 : 0;

        gemm_kernel<<<(nt + 63) / 64, 256, SMEM_GEMM_BYTES>>>(
            x, first, b, Wl[b], Wr[b], bb[b], nt);
        bnscore_kernel<<<(nt + 7) / 8, 256>>>(gw[b], be[b], pp[b], nt, 1.0f / (float)nt, b);
        mega_kernel<<<G_, 1024, MEGA_SMEM>>>(
            ei, b, ncur, k, Wd1, bd1, Wd2, bd2, out);
    }
}

// round 9
// speedup vs baseline: 2.1952x; 1.0106x over previous
#include <cuda_runtime.h>
#include <math.h>
#include <float.h>

// ---------------- problem constants ----------------
#define G_      32
#define EPG     16384                 // edges per graph
#define EDGES   (G_ * EPG)
#define H_      128
#define NT_MAX  32768

static const int NCUR_H[4] = {1024, 820, 656, 525};
static const int KSEL_H[4] = {820, 656, 525, 420};

// gemm smem: meanS 64x132 + W 2x16x128 + H 2x16x64  (floats)
#define SMEM_GEMM_BYTES ((64 * 132 + 2 * 16 * 128 + 2 * 16 * 64) * 4)
// mega smem: 5 x 4KB arrays + 32KB reduce/scratch region
#define MEGA_SMEM (5 * 4096 + 32 * 128 * 2 * 4)

// ---------------- device scratch ----------------
__device__ __align__(16) float g_bufA[NT_MAX * H_];  // pooled h (input of next block)
__device__ __align__(16) float g_bufB[NT_MAX * H_];  // conv out -> BN'd h
__device__ int   g_cnti[NT_MAX];
__device__ int   g_off [NT_MAX];       // absolute csr base per node
__device__ int   g_csr [EDGES];        // neighbor global row ids grouped by dst
__device__ int   g_srcL[EDGES];
__device__ int   g_dstL[EDGES];
__device__ float g_score[NT_MAX];
__device__ __align__(16) float g_colsum[4 * H_];
__device__ __align__(16) float g_colsq [4 * H_];
__device__ float g_flat[G_ * 1024];

// ---------------- csr0: per-graph count+scan+fill for input edges ----------------
__global__ __launch_bounds__(1024)
void csr0_kernel(const int* __restrict__ ei) {
    __shared__ int cnt[1024], off[1024], cur[1024];
    __shared__ int wsum[32];
    int g = blockIdx.x, tid = threadIdx.x;
    int lane = tid & 31, wid = tid >> 5;
    cnt[tid] = 0;
    __syncthreads();
    const int* srcp = ei + g * EPG;
    const int* dstp = ei + EDGES + g * EPG;
    for (int e = tid; e < EPG; e += 1024)
        atomicAdd(&cnt[dstp[e] - (g << 10)], 1);
    __syncthreads();
    int v = cnt[tid];
    int inc = v;
    #pragma unroll
    for (int o = 1; o < 32; o <<= 1) {
        int t = __shfl_up_sync(0xffffffffu, inc, o);
        if (lane >= o) inc += t;
    }
    if (lane == 31) wsum[wid] = inc;
    __syncthreads();
    if (wid == 0) {
        int ws = wsum[lane], wi = ws;
        #pragma unroll
        for (int o = 1; o < 32; o <<= 1) {
            int t = __shfl_up_sync(0xffffffffu, wi, o);
            if (lane >= o) wi += t;
        }
        wsum[lane] = wi - ws;
    }
    __syncthreads();
    int ex = wsum[wid] + inc - v;
    off[tid] = ex;
    g_off [g * 1024 + tid] = g * EPG + ex;
    g_cnti[g * 1024 + tid] = v;
    cur[tid] = 0;
    __syncthreads();
    for (int e = tid; e < EPG; e += 1024) {
        int s = srcp[e];
        int d = dstp[e] - (g << 10);
        int pos = atomicAdd(&cur[d], 1);
        g_csr[g * EPG + off[d] + pos] = s;
    }
    if (g == 0 && tid < 4 * H_) { g_colsum[tid] = 0.f; g_colsq[tid] = 0.f; }
}

// ---------------- fused gather-mean + GEMM + BN-stats (64-row tile) ----------------
__global__ __launch_bounds__(256, 3)
void gemm_kernel(const float* __restrict__ x, int first, int slot,
                 const float* __restrict__ Wl, const float* __restrict__ Wr,
                 const float* __restrict__ bb, int nt) {
    extern __shared__ float smem[];
    float* meanS = smem;                        // [64][132]
    float* WshB  = smem + 64 * 132;             // [2][16][128]
    float* HshB  = WshB + 2 * 16 * 128;         // [2][16][64]
    #define WSH(b,k,c) WshB[(b) * 2048 + (k) * 128 + (c)]
    #define HSH(b,k,m) HshB[(b) * 1024 + (k) * 64 + (m)]

    const float* hin = first ? x : g_bufA;
    int row0 = blockIdx.x * 64;
    int tid = threadIdx.x;
    int w = tid >> 5, lane = tid & 31;
    int tx = tid & 15, ty = tid >> 4;
    int rm = ty * 4, cn = tx * 4;

    // prefetch W block 0 behind the gather
    float4 pw[2];
    #pragma unroll
    for (int i = 0; i < 2; i++) {
        int idx = tid * 2 + i;
        int kk = idx >> 5, c = (idx & 31) * 4;
        pw[i] = *(const float4*)(Wl + (size_t)kk * H_ + c);
    }

    // ---- phase 1: gather means (8 rows per warp, 8 loads in flight) ----
    for (int i = 0; i < 8; i++) {
        int rl = w * 8 + i;
        int row = row0 + rl;
        float4 acc = make_float4(0.f, 0.f, 0.f, 0.f);
        if (row < nt) {
            int deg  = g_cnti[row];
            int base = g_off[row];
            int j = 0;
            for (; j + 8 <= deg; j += 8) {
                int s0 = g_csr[base + j + 0];
                int s1 = g_csr[base + j + 1];
                int s2 = g_csr[base + j + 2];
                int s3 = g_csr[base + j + 3];
                int s4 = g_csr[base + j + 4];
                int s5 = g_csr[base + j + 5];
                int s6 = g_csr[base + j + 6];
                int s7 = g_csr[base + j + 7];
                float4 v0 = *((const float4*)(hin + (size_t)s0 * H_) + lane);
                float4 v1 = *((const float4*)(hin + (size_t)s1 * H_) + lane);
                float4 v2 = *((const float4*)(hin + (size_t)s2 * H_) + lane);
                float4 v3 = *((const float4*)(hin + (size_t)s3 * H_) + lane);
                float4 v4 = *((const float4*)(hin + (size_t)s4 * H_) + lane);
                float4 v5 = *((const float4*)(hin + (size_t)s5 * H_) + lane);
                float4 v6 = *((const float4*)(hin + (size_t)s6 * H_) + lane);
                float4 v7 = *((const float4*)(hin + (size_t)s7 * H_) + lane);
                acc.x += ((v0.x + v1.x) + (v2.x + v3.x)) + ((v4.x + v5.x) + (v6.x + v7.x));
                acc.y += ((v0.y + v1.y) + (v2.y + v3.y)) + ((v4.y + v5.y) + (v6.y + v7.y));
                acc.z += ((v0.z + v1.z) + (v2.z + v3.z)) + ((v4.z + v5.z) + (v6.z + v7.z));
                acc.w += ((v0.w + v1.w) + (v2.w + v3.w)) + ((v4.w + v5.w) + (v6.w + v7.w));
            }
            for (; j < deg; j++) {
                int s0 = g_csr[base + j];
                float4 a = *((const float4*)(hin + (size_t)s0 * H_) + lane);
                acc.x += a.x; acc.y += a.y; acc.z += a.z; acc.w += a.w;
            }
            float inv = 1.0f / fmaxf((float)deg, 1.0f);
            acc.x *= inv; acc.y *= inv; acc.z *= inv; acc.w *= inv;
        }
        *(float4*)&meanS[rl * 132 + lane * 4] = acc;
    }
    #pragma unroll
    for (int i = 0; i < 2; i++) {
        int idx = tid * 2 + i;
        int kk = idx >> 5, c = (idx & 31) * 4;
        *(float4*)&WSH(0, kk, c) = pw[i];
    }
    __syncthreads();

    float acc[4][8];
    #pragma unroll
    for (int i = 0; i < 4; i++)
        #pragma unroll
        for (int j = 0; j < 8; j++) acc[i][j] = 0.f;

    int cur = 0;
    float4 ph;  // single H-tile float4 per thread

    // ---- first half: k = 0..127, A from meanS ----
    for (int kbi = 0; kbi < 8; kbi++) {
        int kwb = (kbi + 1) * 16;
        #pragma unroll
        for (int i = 0; i < 2; i++) {
            int idx = tid * 2 + i;
            int kk = idx >> 5, c = (idx & 31) * 4;
            int kw = kwb + kk;
            const float* ws = (kw < 128) ? (Wl + (size_t)kw * H_ + c)
                                         : (Wr + (size_t)(kw - 128) * H_ + c);
            pw[i] = *(const float4*)ws;
        }
        if (kbi == 7) {
            int r = tid >> 2, kc = (tid & 3) * 4;
            int row = row0 + r;
            ph = (row < nt) ? *(const float4*)(hin + (size_t)row * H_ + kc)
                            : make_float4(0.f, 0.f, 0.f, 0.f);
        }
        int kb = kbi * 16;
        #pragma unroll
        for (int kk = 0; kk < 16; kk++) {
            int kcol = kb + kk;
            float a[4];
            #pragma unroll
            for (int i = 0; i < 4; i++) a[i] = meanS[(rm + i) * 132 + kcol];
            float4 b0 = *(const float4*)&WSH(cur, kk, cn);
            float4 b1 = *(const float4*)&WSH(cur, kk, cn + 64);
            float b[8] = {b0.x, b0.y, b0.z, b0.w, b1.x, b1.y, b1.z, b1.w};
            #pragma unroll
            for (int i = 0; i < 4; i++)
                #pragma unroll
                for (int j = 0; j < 8; j++)
                    acc[i][j] += a[i] * b[j];
        }
        #pragma unroll
        for (int i = 0; i < 2; i++) {
            int idx = tid * 2 + i;
            int kk = idx >> 5, c = (idx & 31) * 4;
            *(float4*)&WSH(cur ^ 1, kk, c) = pw[i];
        }
        if (kbi == 7) {
            int r = tid >> 2, kc = (tid & 3) * 4;
            HSH(cur ^ 1, kc + 0, r) = ph.x;
            HSH(cur ^ 1, kc + 1, r) = ph.y;
            HSH(cur ^ 1, kc + 2, r) = ph.z;
            HSH(cur ^ 1, kc + 3, r) = ph.w;
        }
        __syncthreads();
        cur ^= 1;
    }

    // ---- second half: k = 128..255, A from Hsh ----
    for (int kbi = 8; kbi < 16; kbi++) {
        if (kbi < 15) {
            int kwb = (kbi + 1) * 16;
            int hb  = (kbi + 1 - 8) * 16;
            #pragma unroll
            for (int i = 0; i < 2; i++) {
                int idx = tid * 2 + i;
                int kk = idx >> 5, c = (idx & 31) * 4;
                pw[i] = *(const float4*)(Wr + (size_t)(kwb + kk - 128) * H_ + c);
            }
            int r = tid >> 2, kc = (tid & 3) * 4;
            int row = row0 + r;
            ph = (row < nt) ? *(const float4*)(hin + (size_t)row * H_ + hb + kc)
                            : make_float4(0.f, 0.f, 0.f, 0.f);
        }
        #pragma unroll
        for (int kk = 0; kk < 16; kk++) {
            float4 a0 = *(const float4*)&HSH(cur, kk, rm);
            float4 b0 = *(const float4*)&WSH(cur, kk, cn);
            float4 b1 = *(const float4*)&WSH(cur, kk, cn + 64);
            float a[4] = {a0.x, a0.y, a0.z, a0.w};
            float b[8] = {b0.x, b0.y, b0.z, b0.w, b1.x, b1.y, b1.z, b1.w};
            #pragma unroll
            for (int i = 0; i < 4; i++)
                #pragma unroll
                for (int j = 0; j < 8; j++)
                    acc[i][j] += a[i] * b[j];
        }
        if (kbi < 15) {
            #pragma unroll
            for (int i = 0; i < 2; i++) {
                int idx = tid * 2 + i;
                int kk = idx >> 5, c = (idx & 31) * 4;
                *(float4*)&WSH(cur ^ 1, kk, c) = pw[i];
            }
            int r = tid >> 2, kc = (tid & 3) * 4;
            HSH(cur ^ 1, kc + 0, r) = ph.x;
            HSH(cur ^ 1, kc + 1, r) = ph.y;
            HSH(cur ^ 1, kc + 2, r) = ph.z;
            HSH(cur ^ 1, kc + 3, r) = ph.w;
        }
        __syncthreads();
        cur ^= 1;
    }

    // ---- epilogue ----
    float4 bia0 = *(const float4*)&bb[cn];
    float4 bia1 = *(const float4*)&bb[cn + 64];
    float bias[8] = {bia0.x, bia0.y, bia0.z, bia0.w, bia1.x, bia1.y, bia1.z, bia1.w};
    float psum[8], psq[8];
    #pragma unroll
    for (int j = 0; j < 8; j++) { psum[j] = 0.f; psq[j] = 0.f; }
    #pragma unroll
    for (int i = 0; i < 4; i++) {
        int row = row0 + rm + i;
        if (row < nt) {
            float v[8];
            #pragma unroll
            for (int j = 0; j < 8; j++) {
                v[j] = acc[i][j] + bias[j];
                psum[j] += v[j];
                psq[j]  += v[j] * v[j];
            }
            *(float4*)(g_bufB + (size_t)row * H_ + cn)      = make_float4(v[0], v[1], v[2], v[3]);
            *(float4*)(g_bufB + (size_t)row * H_ + cn + 64) = make_float4(v[4], v[5], v[6], v[7]);
        }
    }
    __syncthreads();
    float* sumS = meanS;          // [16][128]
    float* sqS  = meanS + 2048;   // [16][128]
    #pragma unroll
    for (int j = 0; j < 4; j++) {
        sumS[ty * 128 + cn + j]      = psum[j];
        sumS[ty * 128 + cn + 64 + j] = psum[4 + j];
        sqS [ty * 128 + cn + j]      = psq[j];
        sqS [ty * 128 + cn + 64 + j] = psq[4 + j];
    }
    __syncthreads();
    if (tid < 128) {
        float s = 0.f, q = 0.f;
        #pragma unroll
        for (int t = 0; t < 16; t++) {
            s += sumS[t * 128 + tid];
            q += sqS [t * 128 + tid];
        }
        atomicAdd(&g_colsum[slot * H_ + tid], s);
        atomicAdd(&g_colsq [slot * H_ + tid], q);
    }
    #undef WSH
    #undef HSH
}

// ---------------- wide BN + ReLU + score ----------------
__global__ __launch_bounds__(256)
void bnscore_kernel(const float* __restrict__ gw, const float* __restrict__ be,
                    const float* __restrict__ p, int nt, float invnt, int slot) {
    int row = blockIdx.x * 8 + (threadIdx.x >> 5);
    int lane = threadIdx.x & 31;
    if (row >= nt) return;
    int c = lane * 4;
    float4 h  = *(const float4*)(g_bufB + (size_t)row * H_ + c);
    float4 cs = *(const float4*)&g_colsum[slot * H_ + c];
    float4 cq = *(const float4*)&g_colsq [slot * H_ + c];
    float4 gv = *(const float4*)&gw[c];
    float4 bv = *(const float4*)&be[c];
    float4 pv = *(const float4*)&p[c];
    float hh[4]  = {h.x, h.y, h.z, h.w};
    float css[4] = {cs.x, cs.y, cs.z, cs.w};
    float cqq[4] = {cq.x, cq.y, cq.z, cq.w};
    float gg[4]  = {gv.x, gv.y, gv.z, gv.w};
    float bbv[4] = {bv.x, bv.y, bv.z, bv.w};
    float pp[4]  = {pv.x, pv.y, pv.z, pv.w};
    float out[4];
    float dot = 0.f, pn = 0.f;
    #pragma unroll
    for (int j = 0; j < 4; j++) {
        float mu = css[j] * invnt;
        float var = cqq[j] * invnt - mu * mu;
        float r = rsqrtf(var + 1e-5f);
        float v = (hh[j] - mu) * r * gg[j] + bbv[j];
        v = fmaxf(v, 0.f);
        out[j] = v;
        dot += v * pp[j];
        pn  += pp[j] * pp[j];
    }
    *(float4*)(g_bufB + (size_t)row * H_ + c) = make_float4(out[0], out[1], out[2], out[3]);
    #pragma unroll
    for (int o = 16; o > 0; o >>= 1) {
        dot += __shfl_down_sync(0xffffffffu, dot, o);
        pn  += __shfl_down_sync(0xffffffffu, pn, o);
    }
    if (lane == 0) g_score[row] = dot * rsqrtf(pn);
}

// ---------------- mega: radix-select topk -> gather+readout -> remap+CSR (or MLP head) ----------------
__global__ __launch_bounds__(1024)
void mega_kernel(const int* __restrict__ ei, int b, int ncur, int ksel,
                 const float* __restrict__ Wd1, const float* __restrict__ bd1,
                 const float* __restrict__ Wd2, const float* __restrict__ bd2,
                 float* __restrict__ out) {
    extern __shared__ char smx[];
    float* s_score = (float*)(smx);            // [1024] scores by ORIGINAL id
    int*   s_perm  = (int*)(smx + 4096);       // [1024] new id -> old id; later fill cursors
    int*   s_map   = (int*)(smx + 8192);       // [1024] old id -> new id (-1)
    int*   s_cnt   = (int*)(smx + 12288);
    int*   s_cur   = (int*)(smx + 16384);
    float* s_red   = (float*)(smx + 20480);    // 8192 floats: select scratch, then readout partials

    int g = blockIdx.x, tid = threadIdx.x;
    int lane = tid & 31, wid = tid >> 5;
    int c = lane * 4;

    float myscore = (tid < ncur) ? g_score[g * ncur + tid] : -FLT_MAX;
    s_score[tid] = myscore;

    // orderable key: larger float -> larger uint; padding -> 0
    unsigned int key = 0u;
    if (tid < ncur) {
        unsigned int u = __float_as_uint(myscore);
        key = (u & 0x80000000u) ? ~u : (u | 0x80000000u);
    }

    // ---- radix select: find k-th largest key T and tie budget R ----
    int* hist  = (int*)s_red;        // [256]
    int* hist2 = hist + 256;         // [256]
    int* wtot  = hist + 512;         // [8]
    int* s_sel = hist + 544;         // [2]: digit, count_above
    unsigned int prefixK = 0u, pmask = 0u;
    int remaining = ksel;
    #pragma unroll
    for (int pass = 0; pass < 4; pass++) {
        int shift = 24 - pass * 8;
        if (tid < 256) hist[tid] = 0;
        __syncthreads();
        if ((key & pmask) == prefixK)
            atomicAdd(&hist[(key >> shift) & 255u], 1);
        __syncthreads();
        int inc = 0;
        if (tid < 256) {
            inc = hist[255 - tid];
            #pragma unroll
            for (int o = 1; o < 32; o <<= 1) {
                int t = __shfl_up_sync(0xffffffffu, inc, o);
                if (lane >= o) inc += t;
            }
            if (lane == 31) wtot[tid >> 5] = inc;
        }
        __syncthreads();
        if (tid < 256) {
            int w8 = tid >> 5, add = 0;
            for (int q = 0; q < w8; q++) add += wtot[q];
            hist2[tid] = inc + add;    // suffix sum of bin (255-tid)
        }
        __syncthreads();
        if (tid < 256) {
            int sfx = hist2[tid];
            int above = (tid == 0) ? 0 : hist2[tid - 1];
            if (sfx >= remaining && above < remaining) {
                s_sel[0] = 255 - tid;
                s_sel[1] = above;
            }
        }
        __syncthreads();
        prefixK |= ((unsigned int)s_sel[0]) << shift;
        pmask   |= 255u << shift;
        remaining -= s_sel[1];
        __syncthreads();
    }
    unsigned int T = prefixK;
    int R = remaining;                 // ties (key == T) to accept, by smallest index

    // ---- stable compaction: new ids in original index order ----
    int strict = (key > T) ? 1 : 0;
    int tie    = (key == T) ? 1 : 0;
    int pk = strict | (tie << 16);
    int incs = pk;
    #pragma unroll
    for (int o = 1; o < 32; o <<= 1) {
        int t = __shfl_up_sync(0xffffffffu, incs, o);
        if (lane >= o) incs += t;
    }
    int* wsum = hist;                  // reuse [32]
    if (lane == 31) wsum[wid] = incs;
    __syncthreads();
    if (wid == 0) {
        int ws = wsum[lane], wi = ws;
        #pragma unroll
        for (int o = 1; o < 32; o <<= 1) {
            int t = __shfl_up_sync(0xffffffffu, wi, o);
            if (lane >= o) wi += t;
        }
        wsum[lane] = wi - ws;          // exclusive warp prefix
    }
    __syncthreads();
    int before = wsum[wid] + incs - pk;
    int sk_before  = before & 0xFFFF;
    int tie_before = before >> 16;
    int acc_f = strict | (tie & (tie_before < R ? 1 : 0));
    int newid = sk_before + (tie_before < R ? tie_before : R);
    if (b < 3) s_map[tid] = acc_f ? newid : -1;
    if (acc_f) s_perm[newid] = tid;
    __syncthreads();

    // ---- gather + tanh gate + readout ----
    float4 rsum = make_float4(0.f, 0.f, 0.f, 0.f);
    float4 rmax = make_float4(-FLT_MAX, -FLT_MAX, -FLT_MAX, -FLT_MAX);
    for (int nw = wid; nw < ksel; nw += 32) {
        int old = s_perm[nw];
        float t = tanhf(s_score[old]);
        float4 h = *(const float4*)(g_bufB + (size_t)(g * ncur + old) * H_ + c);
        h.x *= t; h.y *= t; h.z *= t; h.w *= t;
        *(float4*)(g_bufA + (size_t)(g * ksel + nw) * H_ + c) = h;
        rsum.x += h.x; rsum.y += h.y; rsum.z += h.z; rsum.w += h.w;
        rmax.x = fmaxf(rmax.x, h.x); rmax.y = fmaxf(rmax.y, h.y);
        rmax.z = fmaxf(rmax.z, h.z); rmax.w = fmaxf(rmax.w, h.w);
    }
    __syncthreads();   // select scratch in s_red fully consumed before overwrite
    *(float4*)&s_red[wid * 128 + c]        = rsum;
    *(float4*)&s_red[4096 + wid * 128 + c] = rmax;
    __syncthreads();
    if (tid < 128) {
        float s = 0.f, m = -FLT_MAX;
        #pragma unroll
        for (int w = 0; w < 32; w++) {
            s += s_red[w * 128 + tid];
            m = fmaxf(m, s_red[4096 + w * 128 + tid]);
        }
        g_flat[g * 1024 + b * 256 + tid]       = s;
        g_flat[g * 1024 + b * 256 + 128 + tid] = m;
    }
    __syncthreads();

    if (b < 3) {
        // ---- remap + count + scan + fill next-block CSR ----
        for (int i = tid; i < ksel; i += 1024) s_cnt[i] = 0;
        __syncthreads();
        const int eb = g * EPG;
        for (int e = tid; e < EPG; e += 1024) {
            int s, d;
            if (b == 0) { s = ei[eb + e] - (g << 10); d = ei[EDGES + eb + e] - (g << 10); }
            else        { s = g_srcL[eb + e]; d = g_dstL[eb + e]; }
            int ns = -1, nd = -1;
            if (s >= 0) {
                ns = s_map[s];
                nd = s_map[d];
                if (ns < 0 || nd < 0) { ns = -1; nd = -1; }
                else atomicAdd(&s_cnt[nd], 1);
            }
            g_srcL[eb + e] = ns;
            g_dstL[eb + e] = nd;
        }
        __syncthreads();
        int v = (tid < ksel) ? s_cnt[tid] : 0;
        int inc2 = v;
        #pragma unroll
        for (int o = 1; o < 32; o <<= 1) {
            int t = __shfl_up_sync(0xffffffffu, inc2, o);
            if (lane >= o) inc2 += t;
        }
        int* wsum2 = (int*)s_red;
        if (lane == 31) wsum2[wid] = inc2;
        __syncthreads();
        if (wid == 0) {
            int ws = wsum2[lane], wi = ws;
            #pragma unroll
            for (int o = 1; o < 32; o <<= 1) {
                int t = __shfl_up_sync(0xffffffffu, wi, o);
                if (lane >= o) wi += t;
            }
            wsum2[lane] = wi - ws;
        }
        __syncthreads();
        int ex = wsum2[wid] + inc2 - v;
        if (tid < ksel) {
            s_cur[tid] = ex;
            g_off [g * ksel + tid] = eb + ex;
            g_cnti[g * ksel + tid] = v;
            s_perm[tid] = 0;           // reuse as fill cursor
        }
        __syncthreads();
        for (int e = tid; e < EPG; e += 1024) {
            int ns = g_srcL[eb + e];
            if (ns >= 0) {
                int nd = g_dstL[eb + e];
                int pos = atomicAdd(&s_perm[nd], 1);
                g_csr[eb + s_cur[nd] + pos] = g * ksel + ns;
            }
        }
    } else {
        // ---- MLP head per graph ----
        float* a = (float*)s_map;
        a[tid] = g_flat[g * 1024 + tid];
        __syncthreads();
        float* hd = (float*)s_cnt;
        if (tid < 512) {
            float a0 = 0.f, a1 = 0.f, a2 = 0.f, a3 = 0.f;
            #pragma unroll 4
            for (int kk = 0; kk < 1024; kk += 4) {
                a0 += a[kk + 0] * Wd1[(kk + 0) * 512 + tid];
                a1 += a[kk + 1] * Wd1[(kk + 1) * 512 + tid];
                a2 += a[kk + 2] * Wd1[(kk + 2) * 512 + tid];
                a3 += a[kk + 3] * Wd1[(kk + 3) * 512 + tid];
            }
            hd[tid] = fmaxf(a0 + a1 + a2 + a3 + bd1[tid], 0.f);
        }
        __syncthreads();
        if (tid < 320) {
            int cc = tid >> 5, l = tid & 31;
            float acc = 0.f;
            for (int kk = l; kk < 512; kk += 32) acc += hd[kk] * Wd2[kk * 10 + cc];
            #pragma unroll
            for (int o = 16; o > 0; o >>= 1) acc += __shfl_down_sync(0xffffffffu, acc, o);
            if (l == 0) out[g * 10 + cc] = acc + bd2[cc];
        }
    }
}

// ---------------- launcher ----------------
extern "C" void kernel_launch(void* const* d_in, const int* in_sizes, int n_in,
                              void* d_out, int out_size) {
    const float* x  = (const float*)d_in[0];
    const int*   ei = (const int*)d_in[1];
    const float *Wl[4], *Wr[4], *bb[4], *gw[4], *be[4], *pp[4];
    int idx = 3;
    for (int b = 0; b < 4; b++) {
        Wl[b] = (const float*)d_in[idx++];
        Wr[b] = (const float*)d_in[idx++];
        bb[b] = (const float*)d_in[idx++];
        gw[b] = (const float*)d_in[idx++];
        be[b] = (const float*)d_in[idx++];
        pp[b] = (const float*)d_in[idx++];
    }
    const float* Wd1 = (const float*)d_in[27];
    const float* bd1 = (const float*)d_in[28];
    const float* Wd2 = (const float*)d_in[29];
    const float* bd2 = (const float*)d_in[30];
    float* out = (float*)d_out;

    cudaFuncSetAttribute(gemm_kernel, cudaFuncAttributeMaxDynamicSharedMemorySize,
                         SMEM_GEMM_BYTES);
    cudaFuncSetAttribute(mega_kernel, cudaFuncAttributeMaxDynamicSharedMemorySize,
                         MEGA_SMEM);

    csr0_kernel<<<G_, 1024>>>(ei);

    for (int b = 0; b < 4; b++) {
        int ncur = NCUR_H[b];
        int k    = KSEL_H[b];
        int nt   = G_ * ncur;
        int first = (b == 0) ? 1 : 0;

        gemm_kernel<<<(nt + 63) / 64, 256, SMEM_GEMM_BYTES>>>(
            x, first, b, Wl[b], Wr[b], bb[b], nt);
        bnscore_kernel<<<(nt + 7) / 8, 256>>>(gw[b], be[b], pp[b], nt, 1.0f / (float)nt, b);
        mega_kernel<<<G_, 1024, MEGA_SMEM>>>(
            ei, b, ncur, k, Wd1, bd1, Wd2, bd2, out);
    }
}